// round 11
// baseline (speedup 1.0000x reference)
#include <cuda_runtime.h>
#include <cuda_fp16.h>
#include <math.h>
#include <stdint.h>

#define D_MODEL 1024
#define NUM_HEADS 16
#define SEQ 2048
#define BATCH 4
#define D_K 64
#define MTOT (BATCH * SEQ)   // 8192

// fp16 scratch (static device globals; no runtime allocation allowed)
__device__ __align__(16) __half g_xh[MTOT * D_MODEL];
__device__ __align__(16) __half g_qh[MTOT * D_MODEL];
__device__ __align__(16) __half g_kh[MTOT * D_MODEL];
__device__ __align__(16) __half g_vh[MTOT * D_MODEL];
__device__ __align__(16) __half g_oh[MTOT * D_MODEL];
__device__ __align__(16) __half g_wqh[D_MODEL * D_MODEL];
__device__ __align__(16) __half g_wkh[D_MODEL * D_MODEL];
__device__ __align__(16) __half g_wvh[D_MODEL * D_MODEL];
__device__ __align__(16) __half g_woh[D_MODEL * D_MODEL];
__device__ __align__(16) float2 g_rope[SEQ * 32];   // (cos, sin) per (pos, j)

#define QSCALE (0.125f * 1.4426950408889634f)   // 1/sqrt(dk) * log2(e)

// ---------------------------------------------------------------------------
// helpers
// ---------------------------------------------------------------------------
__device__ __forceinline__ uint32_t pack2(float lo, float hi) {
    uint32_t r;
    asm("cvt.rn.f16x2.f32 %0, %1, %2;" : "=r"(r) : "f"(hi), "f"(lo));
    return r;
}

__device__ __forceinline__ float ex2(float x) {
    float r;
    asm("ex2.approx.ftz.f32 %0, %1;" : "=f"(r) : "f"(x));
    return r;
}

__device__ __forceinline__ void mma_f16(float c[4], uint32_t a0, uint32_t a1,
                                        uint32_t a2, uint32_t a3,
                                        uint32_t b0, uint32_t b1) {
    asm volatile(
        "mma.sync.aligned.m16n8k16.row.col.f32.f16.f16.f32 "
        "{%0,%1,%2,%3},{%4,%5,%6,%7},{%8,%9},{%0,%1,%2,%3};"
        : "+f"(c[0]), "+f"(c[1]), "+f"(c[2]), "+f"(c[3])
        : "r"(a0), "r"(a1), "r"(a2), "r"(a3), "r"(b0), "r"(b1));
}

__device__ __forceinline__ void ldm4(uint32_t (&r)[4], uint32_t addr) {
    asm volatile("ldmatrix.sync.aligned.m8n8.x4.shared.b16 {%0,%1,%2,%3}, [%4];"
                 : "=r"(r[0]), "=r"(r[1]), "=r"(r[2]), "=r"(r[3]) : "r"(addr));
}
__device__ __forceinline__ void ldm4t(uint32_t (&r)[4], uint32_t addr) {
    asm volatile("ldmatrix.sync.aligned.m8n8.x4.trans.shared.b16 {%0,%1,%2,%3}, [%4];"
                 : "=r"(r[0]), "=r"(r[1]), "=r"(r[2]), "=r"(r[3]) : "r"(addr));
}

__device__ __forceinline__ uint32_t smem_u32(const void* p) {
    return (uint32_t)__cvta_generic_to_shared(p);
}

__device__ __forceinline__ void cpa(uint32_t dst, const void* src) {
    asm volatile("cp.async.cg.shared.global [%0], [%1], 16;"
                 :: "r"(dst), "l"(src) : "memory");
}
__device__ __forceinline__ void cpa_commit() {
    asm volatile("cp.async.commit_group;" ::: "memory");
}
__device__ __forceinline__ void cpa_wait1() {
    asm volatile("cp.async.wait_group 1;" ::: "memory");
}
__device__ __forceinline__ void cpa_wait0() {
    asm volatile("cp.async.wait_group 0;" ::: "memory");
}

// ---------------------------------------------------------------------------
// pre-pass: fp16 conversions + RoPE table.
// wq folded with 1/sqrt(dk)*log2(e) (exp2-domain softmax).
// ---------------------------------------------------------------------------
__global__ void to_half(const float4* __restrict__ x, const float4* __restrict__ wq,
                        const float4* __restrict__ wk, const float4* __restrict__ wv,
                        const float4* __restrict__ wo, const int* __restrict__ pos)
{
    const int NX = MTOT * D_MODEL / 4;
    const int NW = D_MODEL * D_MODEL / 4;
    const int NR = SEQ * 32;
    const int stride = gridDim.x * blockDim.x;
    uint2* xh = (uint2*)g_xh;
    uint2* wqh = (uint2*)g_wqh;
    uint2* wkh = (uint2*)g_wkh;
    uint2* wvh = (uint2*)g_wvh;
    uint2* woh = (uint2*)g_woh;

    for (int i = blockIdx.x * blockDim.x + threadIdx.x; i < NX; i += stride) {
        float4 v = x[i];
        xh[i] = make_uint2(pack2(v.x, v.y), pack2(v.z, v.w));
    }
    for (int i = blockIdx.x * blockDim.x + threadIdx.x; i < NW; i += stride) {
        float4 a = wq[i];
        wqh[i] = make_uint2(pack2(a.x * QSCALE, a.y * QSCALE),
                            pack2(a.z * QSCALE, a.w * QSCALE));
        float4 b = wk[i];
        wkh[i] = make_uint2(pack2(b.x, b.y), pack2(b.z, b.w));
        float4 c = wv[i];
        wvh[i] = make_uint2(pack2(c.x, c.y), pack2(c.z, c.w));
        float4 d = wo[i];
        woh[i] = make_uint2(pack2(d.x, d.y), pack2(d.z, d.w));
    }
    const float lg = logf(10000.0f);
    for (int i = blockIdx.x * blockDim.x + threadIdx.x; i < NR; i += stride) {
        int s = i >> 5;
        int j = i & 31;
        float invf = expf(-lg * ((float)(2 * j) / (float)D_K));
        float sn, cs;
        sincosf((float)pos[s] * invf, &sn, &cs);
        g_rope[i] = make_float2(cs, sn);
    }
}

// ---------------------------------------------------------------------------
// GEMM: 128x128 block, 4 warps, warp tile 64x64, BK=64, cp.async double-buffer.
// ---------------------------------------------------------------------------
#define GROW 144u
#define GOP (128u * GROW)
#define GSTAGE (2u * GOP)
#define GSMEM (2u * GSTAGE)
#define NKT (D_MODEL / 64)

__device__ __forceinline__ void gemm_mainloop(
    const __half* __restrict__ A, const __half* __restrict__ B,
    int bm, int bn, uint32_t sbase, float (&acc)[4][8][4])
{
    const int tid = threadIdx.x;
    const int lane = tid & 31;
    const int warp = tid >> 5;
    const int warp_m = warp >> 1;
    const int warp_n = warp & 1;

    const int r0 = tid >> 3;
    const int d = tid & 7;

    const uint4* Au4 = (const uint4*)(A + (size_t)bm * D_MODEL);
    const uint4* Bu4 = (const uint4*)(B + (size_t)bn * D_MODEL);

    const int l = lane;
    const uint32_t a_base =
        (uint32_t)(warp_m * 64 + (l & 7) + 8 * ((l >> 3) & 1)) * GROW +
        ((l >> 4) & 1) * 16u;
    const uint32_t b_base =
        (uint32_t)(warp_n * 64 + (l & 7) + 8 * ((l >> 4) & 1)) * GROW +
        ((l >> 3) & 1) * 16u;

    {
        uint32_t as_ = sbase, bs_ = sbase + GOP;
#pragma unroll
        for (int i = 0; i < 8; i++) {
            int row = r0 + 16 * i;
            cpa(as_ + row * GROW + d * 16, Au4 + row * 128 + d);
            cpa(bs_ + row * GROW + d * 16, Bu4 + row * 128 + d);
        }
        cpa_commit();
    }

    for (int kt = 0; kt < NKT; kt++) {
        const uint32_t buf = (uint32_t)(kt & 1);
        if (kt + 1 < NKT) {
            uint32_t as_ = sbase + (buf ^ 1) * GSTAGE;
            uint32_t bs_ = as_ + GOP;
#pragma unroll
            for (int i = 0; i < 8; i++) {
                int row = r0 + 16 * i;
                cpa(as_ + row * GROW + d * 16, Au4 + row * 128 + (kt + 1) * 8 + d);
                cpa(bs_ + row * GROW + d * 16, Bu4 + row * 128 + (kt + 1) * 8 + d);
            }
            cpa_commit();
            cpa_wait1();
        } else {
            cpa_wait0();
        }
        __syncthreads();

        const uint32_t aS = sbase + buf * GSTAGE;
        const uint32_t bS = aS + GOP;
#pragma unroll
        for (int g = 0; g < 4; g++) {
            uint32_t af[4][4], bf[4][4];
#pragma unroll
            for (int mt = 0; mt < 4; mt++)
                ldm4(af[mt], aS + a_base + (uint32_t)mt * 2304u + (uint32_t)g * 32u);
#pragma unroll
            for (int p = 0; p < 4; p++)
                ldm4(bf[p], bS + b_base + (uint32_t)p * 2304u + (uint32_t)g * 32u);
#pragma unroll
            for (int mt = 0; mt < 4; mt++)
#pragma unroll
                for (int nt = 0; nt < 8; nt++)
                    mma_f16(acc[mt][nt], af[mt][0], af[mt][1], af[mt][2], af[mt][3],
                            bf[nt >> 1][(nt & 1) * 2], bf[nt >> 1][(nt & 1) * 2 + 1]);
        }
        __syncthreads();
    }
}

// Fused QKV projection for ONE batch chunk (16 row-blocks).
__global__ __launch_bounds__(128)
void gemm_qkv(int batch)
{
    extern __shared__ __align__(16) uint32_t dsm[];
    const uint32_t sbase = smem_u32(dsm);

    const int mat = blockIdx.x >> 3;
    const int bn = (blockIdx.x & 7) * 128;
    const int bm = (batch * 16 + blockIdx.y) * 128;

    const __half* B = (mat == 0) ? g_wqh : (mat == 1) ? g_wkh : g_wvh;
    __half* C = (mat == 0) ? g_qh : (mat == 1) ? g_kh : g_vh;
    const int rope = (mat < 2);

    float acc[4][8][4];
#pragma unroll
    for (int i = 0; i < 4; i++)
#pragma unroll
        for (int j = 0; j < 8; j++)
#pragma unroll
            for (int v = 0; v < 4; v++) acc[i][j][v] = 0.0f;

    gemm_mainloop(g_xh, B, bm, bn, sbase, acc);

    const int lane = threadIdx.x & 31;
    const int warp = threadIdx.x >> 5;
    const int gid = lane >> 2;
    const int tig = lane & 3;
    const int warp_m = warp >> 1;
    const int warp_n = warp & 1;

    if (rope) {
#pragma unroll
        for (int mt = 0; mt < 4; mt++) {
            int r0 = bm + warp_m * 64 + mt * 16 + gid;
            int s0 = r0 & (SEQ - 1);
            int s1 = (r0 + 8) & (SEQ - 1);
#pragma unroll
            for (int nt = 0; nt < 8; nt++) {
                int c = bn + warp_n * 64 + nt * 8 + 2 * tig;
                int j = (c & (D_K - 1)) >> 1;
                float2 r0v = g_rope[s0 * 32 + j];
                float2 r1v = g_rope[s1 * 32 + j];
                float v0 = acc[mt][nt][0], v1 = acc[mt][nt][1];
                float w0 = acc[mt][nt][2], w1 = acc[mt][nt][3];
                *(uint32_t*)&C[(size_t)r0 * D_MODEL + c] =
                    pack2(v0 * r0v.x - v1 * r0v.y, v0 * r0v.y + v1 * r0v.x);
                *(uint32_t*)&C[(size_t)(r0 + 8) * D_MODEL + c] =
                    pack2(w0 * r1v.x - w1 * r1v.y, w0 * r1v.y + w1 * r1v.x);
            }
        }
    } else {
#pragma unroll
        for (int mt = 0; mt < 4; mt++) {
            int r0 = bm + warp_m * 64 + mt * 16 + gid;
#pragma unroll
            for (int nt = 0; nt < 8; nt++) {
                int c = bn + warp_n * 64 + nt * 8 + 2 * tig;
                *(uint32_t*)&C[(size_t)r0 * D_MODEL + c] =
                    pack2(acc[mt][nt][0], acc[mt][nt][1]);
                *(uint32_t*)&C[(size_t)(r0 + 8) * D_MODEL + c] =
                    pack2(acc[mt][nt][2], acc[mt][nt][3]);
            }
        }
    }
}

// Output projection for ONE batch chunk: fp16 A (g_oh) x fp16 W -> fp32 out
__global__ __launch_bounds__(128)
void gemm_wo(float* __restrict__ C, int batch)
{
    extern __shared__ __align__(16) uint32_t dsm[];
    const uint32_t sbase = smem_u32(dsm);

    const int bn = blockIdx.x * 128;
    const int bm = (batch * 16 + blockIdx.y) * 128;

    float acc[4][8][4];
#pragma unroll
    for (int i = 0; i < 4; i++)
#pragma unroll
        for (int j = 0; j < 8; j++)
#pragma unroll
            for (int v = 0; v < 4; v++) acc[i][j][v] = 0.0f;

    gemm_mainloop(g_oh, g_woh, bm, bn, sbase, acc);

    const int lane = threadIdx.x & 31;
    const int warp = threadIdx.x >> 5;
    const int gid = lane >> 2;
    const int tig = lane & 3;
    const int warp_m = warp >> 1;
    const int warp_n = warp & 1;

#pragma unroll
    for (int mt = 0; mt < 4; mt++) {
        int r0 = bm + warp_m * 64 + mt * 16 + gid;
#pragma unroll
        for (int nt = 0; nt < 8; nt++) {
            int c = bn + warp_n * 64 + nt * 8 + 2 * tig;
            *(float2*)&C[(size_t)r0 * D_MODEL + c] =
                make_float2(acc[mt][nt][0], acc[mt][nt][1]);
            *(float2*)&C[(size_t)(r0 + 8) * D_MODEL + c] =
                make_float2(acc[mt][nt][2], acc[mt][nt][3]);
        }
    }
}

// ---------------------------------------------------------------------------
// Flash attention for ONE batch chunk (16 heads). Br=128 (4 warps x 32 q),
// KV tiles of 64 keys in 3-stage cp.async ring, exp2-domain softmax.
// ---------------------------------------------------------------------------
#define AST 18432u
#define ASMEM (3u * AST)

__global__ __launch_bounds__(128)
void attn_f16(int batch)
{
    extern __shared__ __align__(16) uint32_t asm_[];
    const uint32_t sb = smem_u32(asm_);

    const int tid = threadIdx.x;
    const int warp = tid >> 5;
    const int lane = tid & 31;
    const int gid = lane >> 2;
    const int tig = lane & 3;

    const int qt = (int)gridDim.x - 1 - (int)blockIdx.x;  // heavy blocks first
    const int bh = batch * 16 + blockIdx.y;
    const int q0 = qt * 128;
    const size_t base = (size_t)(bh >> 4) * SEQ * D_MODEL + (size_t)(bh & 15) * D_K;

    const int qw = q0 + warp * 32;
    const int rowmax = qw + 31;

    const int l = lane;
    const uint32_t k_lane =
        (uint32_t)(((l & 7) + 8 * ((l >> 4) & 1)) * 36 + 4 * ((l >> 3) & 1)) * 4;
    const uint32_t v_lane = 9216u +
        (uint32_t)(((l & 7) + 8 * ((l >> 3) & 1)) * 36 + 4 * ((l >> 4) & 1)) * 4;

    uint32_t qa[4][8];
#pragma unroll
    for (int ma = 0; ma < 2; ma++) {
        const __half* Qr0 = g_qh + base + (size_t)(qw + ma * 16 + gid) * D_MODEL;
        const __half* Qr1 = Qr0 + 8 * D_MODEL;
#pragma unroll
        for (int ks = 0; ks < 4; ks++) {
            qa[ks][ma * 4 + 0] = *(const uint32_t*)&Qr0[ks * 16 + 2 * tig];
            qa[ks][ma * 4 + 1] = *(const uint32_t*)&Qr1[ks * 16 + 2 * tig];
            qa[ks][ma * 4 + 2] = *(const uint32_t*)&Qr0[ks * 16 + 2 * tig + 8];
            qa[ks][ma * 4 + 3] = *(const uint32_t*)&Qr1[ks * 16 + 2 * tig + 8];
        }
    }

    float of[2][8][4];
#pragma unroll
    for (int ma = 0; ma < 2; ma++)
#pragma unroll
        for (int i = 0; i < 8; i++)
#pragma unroll
            for (int j = 0; j < 4; j++) of[ma][i][j] = 0.0f;
    float mm[2][2] = {{-1e30f, -1e30f}, {-1e30f, -1e30f}};
    float ll[2][2] = {{0.0f, 0.0f}, {0.0f, 0.0f}};

    const int kr = tid >> 3;
    const int d8 = tid & 7;

    const int nkb = (q0 + 128) / 64;

    {
        const uint4* Kt = (const uint4*)(g_kh + base) + (size_t)kr * 128 + d8;
        const uint4* Vt = (const uint4*)(g_vh + base) + (size_t)kr * 128 + d8;
        uint32_t kd = sb + kr * 144 + d8 * 16;
#pragma unroll
        for (int i = 0; i < 4; i++) {
            cpa(kd + i * 2304u, Kt + (size_t)i * 2048);
            cpa(kd + 9216u + i * 2304u, Vt + (size_t)i * 2048);
        }
        cpa_commit();
    }

    int cs = 0;
    for (int kb = 0; kb < nkb; kb++) {
        const int k0 = kb * 64;
        if (kb + 1 < nkb) {
            int ns = cs + 1; if (ns == 3) ns = 0;
            const uint4* Kt = (const uint4*)(g_kh + base) +
                              ((size_t)(k0 + 64 + kr)) * 128 + d8;
            const uint4* Vt = (const uint4*)(g_vh + base) +
                              ((size_t)(k0 + 64 + kr)) * 128 + d8;
            uint32_t kd = sb + ns * AST + kr * 144 + d8 * 16;
#pragma unroll
            for (int i = 0; i < 4; i++) {
                cpa(kd + i * 2304u, Kt + (size_t)i * 2048);
                cpa(kd + 9216u + i * 2304u, Vt + (size_t)i * 2048);
            }
            cpa_commit();
            cpa_wait1();
        } else {
            cpa_wait0();
        }
        __syncthreads();

        const uint32_t stg = sb + cs * AST;
#pragma unroll
        for (int h = 0; h < 2; h++) {
            const int k0h = k0 + h * 32;
            if (k0h > rowmax) break;
            const uint32_t hoff = (uint32_t)h * 4608u;

            float sc[2][4][4];
#pragma unroll
            for (int ma = 0; ma < 2; ma++)
#pragma unroll
                for (int nt = 0; nt < 4; nt++)
#pragma unroll
                    for (int v = 0; v < 4; v++) sc[ma][nt][v] = 0.0f;
#pragma unroll
            for (int ks = 0; ks < 4; ks++) {
                uint32_t kb0[4], kb1[4];
                ldm4(kb0, stg + k_lane + hoff + (uint32_t)ks * 32u);
                ldm4(kb1, stg + k_lane + hoff + 2304u + (uint32_t)ks * 32u);
#pragma unroll
                for (int ma = 0; ma < 2; ma++) {
                    mma_f16(sc[ma][0], qa[ks][ma*4+0], qa[ks][ma*4+1],
                            qa[ks][ma*4+2], qa[ks][ma*4+3], kb0[0], kb0[1]);
                    mma_f16(sc[ma][1], qa[ks][ma*4+0], qa[ks][ma*4+1],
                            qa[ks][ma*4+2], qa[ks][ma*4+3], kb0[2], kb0[3]);
                    mma_f16(sc[ma][2], qa[ks][ma*4+0], qa[ks][ma*4+1],
                            qa[ks][ma*4+2], qa[ks][ma*4+3], kb1[0], kb1[1]);
                    mma_f16(sc[ma][3], qa[ks][ma*4+0], qa[ks][ma*4+1],
                            qa[ks][ma*4+2], qa[ks][ma*4+3], kb1[2], kb1[3]);
                }
            }

            if (k0h + 31 > qw) {
#pragma unroll
                for (int ma = 0; ma < 2; ma++) {
                    int r0g = qw + ma * 16 + gid;
                    int r1g = r0g + 8;
#pragma unroll
                    for (int nt = 0; nt < 4; nt++) {
                        int c = k0h + nt * 8 + 2 * tig;
                        if (c > r0g)     sc[ma][nt][0] = -1e30f;
                        if (c + 1 > r0g) sc[ma][nt][1] = -1e30f;
                        if (c > r1g)     sc[ma][nt][2] = -1e30f;
                        if (c + 1 > r1g) sc[ma][nt][3] = -1e30f;
                    }
                }
            }

            uint32_t pa[2][2][4];
#pragma unroll
            for (int ma = 0; ma < 2; ma++) {
                float mx0 = sc[ma][0][0], mx1 = sc[ma][0][2];
#pragma unroll
                for (int nt = 0; nt < 4; nt++) {
                    mx0 = fmaxf(mx0, fmaxf(sc[ma][nt][0], sc[ma][nt][1]));
                    mx1 = fmaxf(mx1, fmaxf(sc[ma][nt][2], sc[ma][nt][3]));
                }
                mx0 = fmaxf(mx0, __shfl_xor_sync(0xffffffffu, mx0, 1));
                mx0 = fmaxf(mx0, __shfl_xor_sync(0xffffffffu, mx0, 2));
                mx1 = fmaxf(mx1, __shfl_xor_sync(0xffffffffu, mx1, 1));
                mx1 = fmaxf(mx1, __shfl_xor_sync(0xffffffffu, mx1, 2));

                float mn0 = fmaxf(mm[ma][0], mx0);
                float mn1 = fmaxf(mm[ma][1], mx1);
                float al0 = ex2(mm[ma][0] - mn0);
                float al1 = ex2(mm[ma][1] - mn1);
                mm[ma][0] = mn0; mm[ma][1] = mn1;

                float sum0 = 0.0f, sum1 = 0.0f;
#pragma unroll
                for (int nt = 0; nt < 4; nt++) {
                    sc[ma][nt][0] = ex2(sc[ma][nt][0] - mn0);
                    sc[ma][nt][1] = ex2(sc[ma][nt][1] - mn0);
                    sc[ma][nt][2] = ex2(sc[ma][nt][2] - mn1);
                    sc[ma][nt][3] = ex2(sc[ma][nt][3] - mn1);
                    sum0 += sc[ma][nt][0] + sc[ma][nt][1];
                    sum1 += sc[ma][nt][2] + sc[ma][nt][3];
                }
                sum0 += __shfl_xor_sync(0xffffffffu, sum0, 1);
                sum0 += __shfl_xor_sync(0xffffffffu, sum0, 2);
                sum1 += __shfl_xor_sync(0xffffffffu, sum1, 1);
                sum1 += __shfl_xor_sync(0xffffffffu, sum1, 2);
                ll[ma][0] = ll[ma][0] * al0 + sum0;
                ll[ma][1] = ll[ma][1] * al1 + sum1;

#pragma unroll
                for (int nt = 0; nt < 8; nt++) {
                    of[ma][nt][0] *= al0; of[ma][nt][1] *= al0;
                    of[ma][nt][2] *= al1; of[ma][nt][3] *= al1;
                }

#pragma unroll
                for (int s = 0; s < 2; s++) {
                    pa[ma][s][0] = pack2(sc[ma][2*s][0], sc[ma][2*s][1]);
                    pa[ma][s][1] = pack2(sc[ma][2*s][2], sc[ma][2*s][3]);
                    pa[ma][s][2] = pack2(sc[ma][2*s+1][0], sc[ma][2*s+1][1]);
                    pa[ma][s][3] = pack2(sc[ma][2*s+1][2], sc[ma][2*s+1][3]);
                }
            }

#pragma unroll
            for (int s = 0; s < 2; s++) {
#pragma unroll
                for (int dp = 0; dp < 4; dp++) {
                    uint32_t vb[4];
                    ldm4t(vb, stg + v_lane + hoff + (uint32_t)s * 2304u +
                              (uint32_t)dp * 32u);
#pragma unroll
                    for (int ma = 0; ma < 2; ma++) {
                        mma_f16(of[ma][dp * 2], pa[ma][s][0], pa[ma][s][1],
                                pa[ma][s][2], pa[ma][s][3], vb[0], vb[1]);
                        mma_f16(of[ma][dp * 2 + 1], pa[ma][s][0], pa[ma][s][1],
                                pa[ma][s][2], pa[ma][s][3], vb[2], vb[3]);
                    }
                }
            }
        }
        cs++; if (cs == 3) cs = 0;
    }

#pragma unroll
    for (int ma = 0; ma < 2; ma++) {
        float inv0 = 1.0f / ll[ma][0];
        float inv1 = 1.0f / ll[ma][1];
        __half* O0 = g_oh + base + (size_t)(qw + ma * 16 + gid) * D_MODEL;
        __half* O1 = O0 + 8 * D_MODEL;
#pragma unroll
        for (int nt = 0; nt < 8; nt++) {
            int c = nt * 8 + 2 * tig;
            *(uint32_t*)&O0[c] = pack2(of[ma][nt][0] * inv0, of[ma][nt][1] * inv0);
            *(uint32_t*)&O1[c] = pack2(of[ma][nt][2] * inv1, of[ma][nt][3] * inv1);
        }
    }
}

// ---------------------------------------------------------------------------
// launcher: 3-stage batch pipeline (qkv on capture stream, attn on s1,
// wo on s2), joined back before return. Streams/events created once.
// ---------------------------------------------------------------------------
extern "C" void kernel_launch(void* const* d_in, const int* in_sizes, int n_in,
                              void* d_out, int out_size)
{
    const float* x  = (const float*)d_in[0];
    const float* wq = (const float*)d_in[1];
    const float* wk = (const float*)d_in[2];
    const float* wv = (const float*)d_in[3];
    const float* wo = (const float*)d_in[4];
    const int* tok  = (const int*)d_in[5];
    float* out = (float*)d_out;

    static bool inited = false;
    static cudaStream_t s1, s2;
    static cudaEvent_t evQ[BATCH], evA[BATCH], evW;
    if (!inited) {
        cudaStreamCreateWithFlags(&s1, cudaStreamNonBlocking);
        cudaStreamCreateWithFlags(&s2, cudaStreamNonBlocking);
        for (int b = 0; b < BATCH; b++) {
            cudaEventCreateWithFlags(&evQ[b], cudaEventDisableTiming);
            cudaEventCreateWithFlags(&evA[b], cudaEventDisableTiming);
        }
        cudaEventCreateWithFlags(&evW, cudaEventDisableTiming);
        inited = true;
    }

    cudaFuncSetAttribute(gemm_qkv, cudaFuncAttributeMaxDynamicSharedMemorySize, GSMEM);
    cudaFuncSetAttribute(gemm_wo, cudaFuncAttributeMaxDynamicSharedMemorySize, GSMEM);
    cudaFuncSetAttribute(attn_f16, cudaFuncAttributeMaxDynamicSharedMemorySize, ASMEM);

    to_half<<<2048, 256>>>((const float4*)x, (const float4*)wq,
                           (const float4*)wk, (const float4*)wv,
                           (const float4*)wo, tok);

    for (int b = 0; b < BATCH; b++) {
        dim3 gq(24, 16);
        gemm_qkv<<<gq, 128, GSMEM>>>(b);
        cudaEventRecord(evQ[b], 0);

        cudaStreamWaitEvent(s1, evQ[b], 0);
        dim3 ga(SEQ / 128, 16);
        attn_f16<<<ga, 128, ASMEM, s1>>>(b);
        cudaEventRecord(evA[b], s1);

        cudaStreamWaitEvent(s2, evA[b], 0);
        dim3 gw(D_MODEL / 128, 16);
        gemm_wo<<<gw, 128, GSMEM, s2>>>(out, b);
    }

    // join side streams back into the capture-origin stream
    cudaEventRecord(evW, s2);
    cudaStreamWaitEvent(0, evW, 0);
    cudaStreamWaitEvent(0, evA[BATCH - 1], 0);
}

// round 12
// speedup vs baseline: 1.1166x; 1.1166x over previous
#include <cuda_runtime.h>
#include <cuda_fp16.h>
#include <math.h>
#include <stdint.h>

#define D_MODEL 1024
#define NUM_HEADS 16
#define SEQ 2048
#define BATCH 4
#define D_K 64
#define MTOT (BATCH * SEQ)   // 8192

// fp16 scratch (static device globals; no runtime allocation allowed)
__device__ __align__(16) __half g_xh[MTOT * D_MODEL];
__device__ __align__(16) __half g_qh[MTOT * D_MODEL];
__device__ __align__(16) __half g_kh[MTOT * D_MODEL];
__device__ __align__(16) __half g_vh[MTOT * D_MODEL];
__device__ __align__(16) __half g_oh[MTOT * D_MODEL];
__device__ __align__(16) __half g_wqh[D_MODEL * D_MODEL];
__device__ __align__(16) __half g_wkh[D_MODEL * D_MODEL];
__device__ __align__(16) __half g_wvh[D_MODEL * D_MODEL];
__device__ __align__(16) __half g_woh[D_MODEL * D_MODEL];
__device__ __align__(16) float2 g_rope[SEQ * 32];   // (cos, sin) per (pos, j)

#define QSCALE (0.125f * 1.4426950408889634f)   // 1/sqrt(dk) * log2(e)

// ---------------------------------------------------------------------------
// helpers
// ---------------------------------------------------------------------------
__device__ __forceinline__ uint32_t pack2(float lo, float hi) {
    uint32_t r;
    asm("cvt.rn.f16x2.f32 %0, %1, %2;" : "=r"(r) : "f"(hi), "f"(lo));
    return r;
}

__device__ __forceinline__ float ex2(float x) {
    float r;
    asm("ex2.approx.ftz.f32 %0, %1;" : "=f"(r) : "f"(x));
    return r;
}

__device__ __forceinline__ void mma_f16(float c[4], uint32_t a0, uint32_t a1,
                                        uint32_t a2, uint32_t a3,
                                        uint32_t b0, uint32_t b1) {
    asm volatile(
        "mma.sync.aligned.m16n8k16.row.col.f32.f16.f16.f32 "
        "{%0,%1,%2,%3},{%4,%5,%6,%7},{%8,%9},{%0,%1,%2,%3};"
        : "+f"(c[0]), "+f"(c[1]), "+f"(c[2]), "+f"(c[3])
        : "r"(a0), "r"(a1), "r"(a2), "r"(a3), "r"(b0), "r"(b1));
}

__device__ __forceinline__ void ldm4(uint32_t (&r)[4], uint32_t addr) {
    asm volatile("ldmatrix.sync.aligned.m8n8.x4.shared.b16 {%0,%1,%2,%3}, [%4];"
                 : "=r"(r[0]), "=r"(r[1]), "=r"(r[2]), "=r"(r[3]) : "r"(addr));
}
__device__ __forceinline__ void ldm4t(uint32_t (&r)[4], uint32_t addr) {
    asm volatile("ldmatrix.sync.aligned.m8n8.x4.trans.shared.b16 {%0,%1,%2,%3}, [%4];"
                 : "=r"(r[0]), "=r"(r[1]), "=r"(r[2]), "=r"(r[3]) : "r"(addr));
}

__device__ __forceinline__ uint32_t smem_u32(const void* p) {
    return (uint32_t)__cvta_generic_to_shared(p);
}

__device__ __forceinline__ void cpa(uint32_t dst, const void* src) {
    asm volatile("cp.async.cg.shared.global [%0], [%1], 16;"
                 :: "r"(dst), "l"(src) : "memory");
}
__device__ __forceinline__ void cpa_commit() {
    asm volatile("cp.async.commit_group;" ::: "memory");
}
__device__ __forceinline__ void cpa_wait1() {
    asm volatile("cp.async.wait_group 1;" ::: "memory");
}
__device__ __forceinline__ void cpa_wait0() {
    asm volatile("cp.async.wait_group 0;" ::: "memory");
}

// ---------------------------------------------------------------------------
// pre-pass: fp16 conversions + RoPE table.
// wq folded with 1/sqrt(dk)*log2(e) (exp2-domain softmax).
// ---------------------------------------------------------------------------
__global__ void to_half(const float4* __restrict__ x, const float4* __restrict__ wq,
                        const float4* __restrict__ wk, const float4* __restrict__ wv,
                        const float4* __restrict__ wo, const int* __restrict__ pos)
{
    const int NX = MTOT * D_MODEL / 4;
    const int NW = D_MODEL * D_MODEL / 4;
    const int NR = SEQ * 32;
    const int stride = gridDim.x * blockDim.x;
    uint2* xh = (uint2*)g_xh;
    uint2* wqh = (uint2*)g_wqh;
    uint2* wkh = (uint2*)g_wkh;
    uint2* wvh = (uint2*)g_wvh;
    uint2* woh = (uint2*)g_woh;

    for (int i = blockIdx.x * blockDim.x + threadIdx.x; i < NX; i += stride) {
        float4 v = x[i];
        xh[i] = make_uint2(pack2(v.x, v.y), pack2(v.z, v.w));
    }
    for (int i = blockIdx.x * blockDim.x + threadIdx.x; i < NW; i += stride) {
        float4 a = wq[i];
        wqh[i] = make_uint2(pack2(a.x * QSCALE, a.y * QSCALE),
                            pack2(a.z * QSCALE, a.w * QSCALE));
        float4 b = wk[i];
        wkh[i] = make_uint2(pack2(b.x, b.y), pack2(b.z, b.w));
        float4 c = wv[i];
        wvh[i] = make_uint2(pack2(c.x, c.y), pack2(c.z, c.w));
        float4 d = wo[i];
        woh[i] = make_uint2(pack2(d.x, d.y), pack2(d.z, d.w));
    }
    const float lg = logf(10000.0f);
    for (int i = blockIdx.x * blockDim.x + threadIdx.x; i < NR; i += stride) {
        int s = i >> 5;
        int j = i & 31;
        float invf = expf(-lg * ((float)(2 * j) / (float)D_K));
        float sn, cs;
        sincosf((float)pos[s] * invf, &sn, &cs);
        g_rope[i] = make_float2(cs, sn);
    }
}

// ---------------------------------------------------------------------------
// GEMM: 64x128 block tile, 4 warps (2x2), warp tile 32x64, BK=64,
// cp.async double-buffer. smem rows 144B (odd*16B mod 128 -> ldmatrix
// conflict-free; 8 threads/row STS hits 8 distinct bank groups).
// Small tiles -> ~110 regs -> 4 CTAs/SM (592 slots) for better wave packing.
// ---------------------------------------------------------------------------
#define GROW 144u
#define AOP (64u * GROW)          // A tile bytes (9216)
#define BOP (128u * GROW)         // B tile bytes (18432)
#define GSTAGE (AOP + BOP)        // 27648
#define GSMEM (2u * GSTAGE)       // 55296
#define NKT (D_MODEL / 64)        // 16

__device__ __forceinline__ void gemm_mainloop(
    const __half* __restrict__ A, const __half* __restrict__ B,
    int bm, int bn, uint32_t sbase, float (&acc)[2][8][4])
{
    const int tid = threadIdx.x;
    const int lane = tid & 31;
    const int warp = tid >> 5;
    const int warp_m = warp >> 1;    // 0..1
    const int warp_n = warp & 1;     // 0..1

    const int r0 = tid >> 3;         // 0..15
    const int d = tid & 7;           // uint4 col within 64-wide k chunk

    const uint4* Au4 = (const uint4*)(A + (size_t)bm * D_MODEL);
    const uint4* Bu4 = (const uint4*)(B + (size_t)bn * D_MODEL);

    const int l = lane;
    const uint32_t a_base =
        (uint32_t)(warp_m * 32 + (l & 7) + 8 * ((l >> 3) & 1)) * GROW +
        ((l >> 4) & 1) * 16u;
    const uint32_t b_base = AOP +
        (uint32_t)(warp_n * 64 + (l & 7) + 8 * ((l >> 4) & 1)) * GROW +
        ((l >> 3) & 1) * 16u;

    // prologue: stage 0
    {
        uint32_t as_ = sbase, bs_ = sbase + AOP;
#pragma unroll
        for (int i = 0; i < 4; i++) {
            int row = r0 + 16 * i;
            cpa(as_ + row * GROW + d * 16, Au4 + row * 128 + d);
        }
#pragma unroll
        for (int i = 0; i < 8; i++) {
            int row = r0 + 16 * i;
            cpa(bs_ + row * GROW + d * 16, Bu4 + row * 128 + d);
        }
        cpa_commit();
    }

    for (int kt = 0; kt < NKT; kt++) {
        const uint32_t buf = (uint32_t)(kt & 1);
        if (kt + 1 < NKT) {
            uint32_t as_ = sbase + (buf ^ 1) * GSTAGE;
            uint32_t bs_ = as_ + AOP;
#pragma unroll
            for (int i = 0; i < 4; i++) {
                int row = r0 + 16 * i;
                cpa(as_ + row * GROW + d * 16, Au4 + row * 128 + (kt + 1) * 8 + d);
            }
#pragma unroll
            for (int i = 0; i < 8; i++) {
                int row = r0 + 16 * i;
                cpa(bs_ + row * GROW + d * 16, Bu4 + row * 128 + (kt + 1) * 8 + d);
            }
            cpa_commit();
            cpa_wait1();
        } else {
            cpa_wait0();
        }
        __syncthreads();

        const uint32_t aS = sbase + buf * GSTAGE;
#pragma unroll
        for (int g = 0; g < 4; g++) {
            uint32_t af[2][4], bf[4][4];
#pragma unroll
            for (int mt = 0; mt < 2; mt++)
                ldm4(af[mt], aS + a_base + (uint32_t)mt * 2304u + (uint32_t)g * 32u);
#pragma unroll
            for (int p = 0; p < 4; p++)
                ldm4(bf[p], aS + b_base + (uint32_t)p * 2304u + (uint32_t)g * 32u);
#pragma unroll
            for (int mt = 0; mt < 2; mt++)
#pragma unroll
                for (int nt = 0; nt < 8; nt++)
                    mma_f16(acc[mt][nt], af[mt][0], af[mt][1], af[mt][2], af[mt][3],
                            bf[nt >> 1][(nt & 1) * 2], bf[nt >> 1][(nt & 1) * 2 + 1]);
        }
        __syncthreads();
    }
}

// Fused QKV projection; RoPE via precomputed table. grid (24, 128).
__global__ __launch_bounds__(128)
void gemm_qkv()
{
    extern __shared__ __align__(16) uint32_t dsm[];
    const uint32_t sbase = smem_u32(dsm);

    const int mat = blockIdx.x >> 3;
    const int bn = (blockIdx.x & 7) * 128;
    const int bm = blockIdx.y * 64;

    const __half* B = (mat == 0) ? g_wqh : (mat == 1) ? g_wkh : g_wvh;
    __half* C = (mat == 0) ? g_qh : (mat == 1) ? g_kh : g_vh;
    const int rope = (mat < 2);

    float acc[2][8][4];
#pragma unroll
    for (int i = 0; i < 2; i++)
#pragma unroll
        for (int j = 0; j < 8; j++)
#pragma unroll
            for (int v = 0; v < 4; v++) acc[i][j][v] = 0.0f;

    gemm_mainloop(g_xh, B, bm, bn, sbase, acc);

    const int lane = threadIdx.x & 31;
    const int warp = threadIdx.x >> 5;
    const int gid = lane >> 2;
    const int tig = lane & 3;
    const int warp_m = warp >> 1;
    const int warp_n = warp & 1;

    if (rope) {
#pragma unroll
        for (int mt = 0; mt < 2; mt++) {
            int r0 = bm + warp_m * 32 + mt * 16 + gid;
            int s0 = r0 & (SEQ - 1);
            int s1 = (r0 + 8) & (SEQ - 1);
#pragma unroll
            for (int nt = 0; nt < 8; nt++) {
                int c = bn + warp_n * 64 + nt * 8 + 2 * tig;
                int j = (c & (D_K - 1)) >> 1;
                float2 r0v = g_rope[s0 * 32 + j];
                float2 r1v = g_rope[s1 * 32 + j];
                float v0 = acc[mt][nt][0], v1 = acc[mt][nt][1];
                float w0 = acc[mt][nt][2], w1 = acc[mt][nt][3];
                *(uint32_t*)&C[(size_t)r0 * D_MODEL + c] =
                    pack2(v0 * r0v.x - v1 * r0v.y, v0 * r0v.y + v1 * r0v.x);
                *(uint32_t*)&C[(size_t)(r0 + 8) * D_MODEL + c] =
                    pack2(w0 * r1v.x - w1 * r1v.y, w0 * r1v.y + w1 * r1v.x);
            }
        }
    } else {
#pragma unroll
        for (int mt = 0; mt < 2; mt++) {
            int r0 = bm + warp_m * 32 + mt * 16 + gid;
#pragma unroll
            for (int nt = 0; nt < 8; nt++) {
                int c = bn + warp_n * 64 + nt * 8 + 2 * tig;
                *(uint32_t*)&C[(size_t)r0 * D_MODEL + c] =
                    pack2(acc[mt][nt][0], acc[mt][nt][1]);
                *(uint32_t*)&C[(size_t)(r0 + 8) * D_MODEL + c] =
                    pack2(acc[mt][nt][2], acc[mt][nt][3]);
            }
        }
    }
}

// Output projection: fp16 A (g_oh) x fp16 W -> fp32 out. grid (8, 128).
__global__ __launch_bounds__(128)
void gemm_wo(float* __restrict__ C)
{
    extern __shared__ __align__(16) uint32_t dsm[];
    const uint32_t sbase = smem_u32(dsm);

    const int bn = blockIdx.x * 128;
    const int bm = blockIdx.y * 64;

    float acc[2][8][4];
#pragma unroll
    for (int i = 0; i < 2; i++)
#pragma unroll
        for (int j = 0; j < 8; j++)
#pragma unroll
            for (int v = 0; v < 4; v++) acc[i][j][v] = 0.0f;

    gemm_mainloop(g_oh, g_woh, bm, bn, sbase, acc);

    const int lane = threadIdx.x & 31;
    const int warp = threadIdx.x >> 5;
    const int gid = lane >> 2;
    const int tig = lane & 3;
    const int warp_m = warp >> 1;
    const int warp_n = warp & 1;

#pragma unroll
    for (int mt = 0; mt < 2; mt++) {
        int r0 = bm + warp_m * 32 + mt * 16 + gid;
#pragma unroll
        for (int nt = 0; nt < 8; nt++) {
            int c = bn + warp_n * 64 + nt * 8 + 2 * tig;
            *(float2*)&C[(size_t)r0 * D_MODEL + c] =
                make_float2(acc[mt][nt][0], acc[mt][nt][1]);
            *(float2*)&C[(size_t)(r0 + 8) * D_MODEL + c] =
                make_float2(acc[mt][nt][2], acc[mt][nt][3]);
        }
    }
}

// ---------------------------------------------------------------------------
// Flash attention (identical to round 10): Br=128 (4 warps x 32 q), KV tiles
// of 64 keys in 3-stage cp.async ring, exp2-domain softmax.
// ---------------------------------------------------------------------------
#define AST 18432u
#define ASMEM (3u * AST)

__global__ __launch_bounds__(128)
void attn_f16()
{
    extern __shared__ __align__(16) uint32_t asm_[];
    const uint32_t sb = smem_u32(asm_);

    const int tid = threadIdx.x;
    const int warp = tid >> 5;
    const int lane = tid & 31;
    const int gid = lane >> 2;
    const int tig = lane & 3;

    const int qt = (int)gridDim.x - 1 - (int)blockIdx.x;  // heavy blocks first
    const int bh = blockIdx.y;
    const int q0 = qt * 128;
    const size_t base = (size_t)(bh >> 4) * SEQ * D_MODEL + (size_t)(bh & 15) * D_K;

    const int qw = q0 + warp * 32;
    const int rowmax = qw + 31;

    const int l = lane;
    const uint32_t k_lane =
        (uint32_t)(((l & 7) + 8 * ((l >> 4) & 1)) * 36 + 4 * ((l >> 3) & 1)) * 4;
    const uint32_t v_lane = 9216u +
        (uint32_t)(((l & 7) + 8 * ((l >> 3) & 1)) * 36 + 4 * ((l >> 4) & 1)) * 4;

    uint32_t qa[4][8];
#pragma unroll
    for (int ma = 0; ma < 2; ma++) {
        const __half* Qr0 = g_qh + base + (size_t)(qw + ma * 16 + gid) * D_MODEL;
        const __half* Qr1 = Qr0 + 8 * D_MODEL;
#pragma unroll
        for (int ks = 0; ks < 4; ks++) {
            qa[ks][ma * 4 + 0] = *(const uint32_t*)&Qr0[ks * 16 + 2 * tig];
            qa[ks][ma * 4 + 1] = *(const uint32_t*)&Qr1[ks * 16 + 2 * tig];
            qa[ks][ma * 4 + 2] = *(const uint32_t*)&Qr0[ks * 16 + 2 * tig + 8];
            qa[ks][ma * 4 + 3] = *(const uint32_t*)&Qr1[ks * 16 + 2 * tig + 8];
        }
    }

    float of[2][8][4];
#pragma unroll
    for (int ma = 0; ma < 2; ma++)
#pragma unroll
        for (int i = 0; i < 8; i++)
#pragma unroll
            for (int j = 0; j < 4; j++) of[ma][i][j] = 0.0f;
    float mm[2][2] = {{-1e30f, -1e30f}, {-1e30f, -1e30f}};
    float ll[2][2] = {{0.0f, 0.0f}, {0.0f, 0.0f}};

    const int kr = tid >> 3;
    const int d8 = tid & 7;

    const int nkb = (q0 + 128) / 64;

    {
        const uint4* Kt = (const uint4*)(g_kh + base) + (size_t)kr * 128 + d8;
        const uint4* Vt = (const uint4*)(g_vh + base) + (size_t)kr * 128 + d8;
        uint32_t kd = sb + kr * 144 + d8 * 16;
#pragma unroll
        for (int i = 0; i < 4; i++) {
            cpa(kd + i * 2304u, Kt + (size_t)i * 2048);
            cpa(kd + 9216u + i * 2304u, Vt + (size_t)i * 2048);
        }
        cpa_commit();
    }

    int cs = 0;
    for (int kb = 0; kb < nkb; kb++) {
        const int k0 = kb * 64;
        if (kb + 1 < nkb) {
            int ns = cs + 1; if (ns == 3) ns = 0;
            const uint4* Kt = (const uint4*)(g_kh + base) +
                              ((size_t)(k0 + 64 + kr)) * 128 + d8;
            const uint4* Vt = (const uint4*)(g_vh + base) +
                              ((size_t)(k0 + 64 + kr)) * 128 + d8;
            uint32_t kd = sb + ns * AST + kr * 144 + d8 * 16;
#pragma unroll
            for (int i = 0; i < 4; i++) {
                cpa(kd + i * 2304u, Kt + (size_t)i * 2048);
                cpa(kd + 9216u + i * 2304u, Vt + (size_t)i * 2048);
            }
            cpa_commit();
            cpa_wait1();
        } else {
            cpa_wait0();
        }
        __syncthreads();

        const uint32_t stg = sb + cs * AST;
#pragma unroll
        for (int h = 0; h < 2; h++) {
            const int k0h = k0 + h * 32;
            if (k0h > rowmax) break;
            const uint32_t hoff = (uint32_t)h * 4608u;

            float sc[2][4][4];
#pragma unroll
            for (int ma = 0; ma < 2; ma++)
#pragma unroll
                for (int nt = 0; nt < 4; nt++)
#pragma unroll
                    for (int v = 0; v < 4; v++) sc[ma][nt][v] = 0.0f;
#pragma unroll
            for (int ks = 0; ks < 4; ks++) {
                uint32_t kb0[4], kb1[4];
                ldm4(kb0, stg + k_lane + hoff + (uint32_t)ks * 32u);
                ldm4(kb1, stg + k_lane + hoff + 2304u + (uint32_t)ks * 32u);
#pragma unroll
                for (int ma = 0; ma < 2; ma++) {
                    mma_f16(sc[ma][0], qa[ks][ma*4+0], qa[ks][ma*4+1],
                            qa[ks][ma*4+2], qa[ks][ma*4+3], kb0[0], kb0[1]);
                    mma_f16(sc[ma][1], qa[ks][ma*4+0], qa[ks][ma*4+1],
                            qa[ks][ma*4+2], qa[ks][ma*4+3], kb0[2], kb0[3]);
                    mma_f16(sc[ma][2], qa[ks][ma*4+0], qa[ks][ma*4+1],
                            qa[ks][ma*4+2], qa[ks][ma*4+3], kb1[0], kb1[1]);
                    mma_f16(sc[ma][3], qa[ks][ma*4+0], qa[ks][ma*4+1],
                            qa[ks][ma*4+2], qa[ks][ma*4+3], kb1[2], kb1[3]);
                }
            }

            if (k0h + 31 > qw) {
#pragma unroll
                for (int ma = 0; ma < 2; ma++) {
                    int r0g = qw + ma * 16 + gid;
                    int r1g = r0g + 8;
#pragma unroll
                    for (int nt = 0; nt < 4; nt++) {
                        int c = k0h + nt * 8 + 2 * tig;
                        if (c > r0g)     sc[ma][nt][0] = -1e30f;
                        if (c + 1 > r0g) sc[ma][nt][1] = -1e30f;
                        if (c > r1g)     sc[ma][nt][2] = -1e30f;
                        if (c + 1 > r1g) sc[ma][nt][3] = -1e30f;
                    }
                }
            }

            uint32_t pa[2][2][4];
#pragma unroll
            for (int ma = 0; ma < 2; ma++) {
                float mx0 = sc[ma][0][0], mx1 = sc[ma][0][2];
#pragma unroll
                for (int nt = 0; nt < 4; nt++) {
                    mx0 = fmaxf(mx0, fmaxf(sc[ma][nt][0], sc[ma][nt][1]));
                    mx1 = fmaxf(mx1, fmaxf(sc[ma][nt][2], sc[ma][nt][3]));
                }
                mx0 = fmaxf(mx0, __shfl_xor_sync(0xffffffffu, mx0, 1));
                mx0 = fmaxf(mx0, __shfl_xor_sync(0xffffffffu, mx0, 2));
                mx1 = fmaxf(mx1, __shfl_xor_sync(0xffffffffu, mx1, 1));
                mx1 = fmaxf(mx1, __shfl_xor_sync(0xffffffffu, mx1, 2));

                float mn0 = fmaxf(mm[ma][0], mx0);
                float mn1 = fmaxf(mm[ma][1], mx1);
                float al0 = ex2(mm[ma][0] - mn0);
                float al1 = ex2(mm[ma][1] - mn1);
                mm[ma][0] = mn0; mm[ma][1] = mn1;

                float sum0 = 0.0f, sum1 = 0.0f;
#pragma unroll
                for (int nt = 0; nt < 4; nt++) {
                    sc[ma][nt][0] = ex2(sc[ma][nt][0] - mn0);
                    sc[ma][nt][1] = ex2(sc[ma][nt][1] - mn0);
                    sc[ma][nt][2] = ex2(sc[ma][nt][2] - mn1);
                    sc[ma][nt][3] = ex2(sc[ma][nt][3] - mn1);
                    sum0 += sc[ma][nt][0] + sc[ma][nt][1];
                    sum1 += sc[ma][nt][2] + sc[ma][nt][3];
                }
                sum0 += __shfl_xor_sync(0xffffffffu, sum0, 1);
                sum0 += __shfl_xor_sync(0xffffffffu, sum0, 2);
                sum1 += __shfl_xor_sync(0xffffffffu, sum1, 1);
                sum1 += __shfl_xor_sync(0xffffffffu, sum1, 2);
                ll[ma][0] = ll[ma][0] * al0 + sum0;
                ll[ma][1] = ll[ma][1] * al1 + sum1;

#pragma unroll
                for (int nt = 0; nt < 8; nt++) {
                    of[ma][nt][0] *= al0; of[ma][nt][1] *= al0;
                    of[ma][nt][2] *= al1; of[ma][nt][3] *= al1;
                }

#pragma unroll
                for (int s = 0; s < 2; s++) {
                    pa[ma][s][0] = pack2(sc[ma][2*s][0], sc[ma][2*s][1]);
                    pa[ma][s][1] = pack2(sc[ma][2*s][2], sc[ma][2*s][3]);
                    pa[ma][s][2] = pack2(sc[ma][2*s+1][0], sc[ma][2*s+1][1]);
                    pa[ma][s][3] = pack2(sc[ma][2*s+1][2], sc[ma][2*s+1][3]);
                }
            }

#pragma unroll
            for (int s = 0; s < 2; s++) {
#pragma unroll
                for (int dp = 0; dp < 4; dp++) {
                    uint32_t vb[4];
                    ldm4t(vb, stg + v_lane + hoff + (uint32_t)s * 2304u +
                              (uint32_t)dp * 32u);
#pragma unroll
                    for (int ma = 0; ma < 2; ma++) {
                        mma_f16(of[ma][dp * 2], pa[ma][s][0], pa[ma][s][1],
                                pa[ma][s][2], pa[ma][s][3], vb[0], vb[1]);
                        mma_f16(of[ma][dp * 2 + 1], pa[ma][s][0], pa[ma][s][1],
                                pa[ma][s][2], pa[ma][s][3], vb[2], vb[3]);
                    }
                }
            }
        }
        cs++; if (cs == 3) cs = 0;
    }

#pragma unroll
    for (int ma = 0; ma < 2; ma++) {
        float inv0 = 1.0f / ll[ma][0];
        float inv1 = 1.0f / ll[ma][1];
        __half* O0 = g_oh + base + (size_t)(qw + ma * 16 + gid) * D_MODEL;
        __half* O1 = O0 + 8 * D_MODEL;
#pragma unroll
        for (int nt = 0; nt < 8; nt++) {
            int c = nt * 8 + 2 * tig;
            *(uint32_t*)&O0[c] = pack2(of[ma][nt][0] * inv0, of[ma][nt][1] * inv0);
            *(uint32_t*)&O1[c] = pack2(of[ma][nt][2] * inv1, of[ma][nt][3] * inv1);
        }
    }
}

// ---------------------------------------------------------------------------
extern "C" void kernel_launch(void* const* d_in, const int* in_sizes, int n_in,
                              void* d_out, int out_size)
{
    const float* x  = (const float*)d_in[0];
    const float* wq = (const float*)d_in[1];
    const float* wk = (const float*)d_in[2];
    const float* wv = (const float*)d_in[3];
    const float* wo = (const float*)d_in[4];
    const int* tok  = (const int*)d_in[5];
    float* out = (float*)d_out;

    cudaFuncSetAttribute(gemm_qkv, cudaFuncAttributeMaxDynamicSharedMemorySize, GSMEM);
    cudaFuncSetAttribute(gemm_wo, cudaFuncAttributeMaxDynamicSharedMemorySize, GSMEM);
    cudaFuncSetAttribute(attn_f16, cudaFuncAttributeMaxDynamicSharedMemorySize, ASMEM);

    to_half<<<2048, 256>>>((const float4*)x, (const float4*)wq,
                           (const float4*)wk, (const float4*)wv,
                           (const float4*)wo, tok);

    dim3 gq(24, MTOT / 64);    // (24, 128) fused QKV
    gemm_qkv<<<gq, 128, GSMEM>>>();

    dim3 ga(SEQ / 128, BATCH * NUM_HEADS);
    attn_f16<<<ga, 128, ASMEM>>>();

    dim3 gw(D_MODEL / 128, MTOT / 64);   // (8, 128)
    gemm_wo<<<gw, 128, GSMEM>>>(out);
}

// round 14
// speedup vs baseline: 1.1407x; 1.0216x over previous
#include <cuda_runtime.h>
#include <cuda_fp16.h>
#include <math.h>
#include <stdint.h>

#define D_MODEL 1024
#define NUM_HEADS 16
#define SEQ 2048
#define BATCH 4
#define D_K 64
#define MTOT (BATCH * SEQ)   // 8192

// fp16 scratch (static device globals; no runtime allocation allowed)
__device__ __align__(16) __half g_xh[MTOT * D_MODEL];
__device__ __align__(16) __half g_qh[MTOT * D_MODEL];
__device__ __align__(16) __half g_kh[MTOT * D_MODEL];
__device__ __align__(16) __half g_vh[MTOT * D_MODEL];
__device__ __align__(16) __half g_oh[MTOT * D_MODEL];
__device__ __align__(16) __half g_wqh[D_MODEL * D_MODEL];
__device__ __align__(16) __half g_wkh[D_MODEL * D_MODEL];
__device__ __align__(16) __half g_wvh[D_MODEL * D_MODEL];
__device__ __align__(16) __half g_woh[D_MODEL * D_MODEL];
__device__ __align__(16) float2 g_rope[SEQ * 32];   // (cos, sin) per (pos, j)

#define QSCALE (0.125f * 1.4426950408889634f)   // 1/sqrt(dk) * log2(e)

// ---------------------------------------------------------------------------
// helpers
// ---------------------------------------------------------------------------
__device__ __forceinline__ uint32_t pack2(float lo, float hi) {
    uint32_t r;
    asm("cvt.rn.f16x2.f32 %0, %1, %2;" : "=r"(r) : "f"(hi), "f"(lo));
    return r;
}

__device__ __forceinline__ float ex2(float x) {
    float r;
    asm("ex2.approx.ftz.f32 %0, %1;" : "=f"(r) : "f"(x));
    return r;
}

// PDL: wait for the preceding grid (only needed before touching its outputs)
__device__ __forceinline__ void gdc_wait() {
    asm volatile("griddepcontrol.wait;" ::: "memory");
}

__device__ __forceinline__ void mma_f16(float c[4], uint32_t a0, uint32_t a1,
                                        uint32_t a2, uint32_t a3,
                                        uint32_t b0, uint32_t b1) {
    asm volatile(
        "mma.sync.aligned.m16n8k16.row.col.f32.f16.f16.f32 "
        "{%0,%1,%2,%3},{%4,%5,%6,%7},{%8,%9},{%0,%1,%2,%3};"
        : "+f"(c[0]), "+f"(c[1]), "+f"(c[2]), "+f"(c[3])
        : "r"(a0), "r"(a1), "r"(a2), "r"(a3), "r"(b0), "r"(b1));
}

__device__ __forceinline__ void ldm4(uint32_t (&r)[4], uint32_t addr) {
    asm volatile("ldmatrix.sync.aligned.m8n8.x4.shared.b16 {%0,%1,%2,%3}, [%4];"
                 : "=r"(r[0]), "=r"(r[1]), "=r"(r[2]), "=r"(r[3]) : "r"(addr));
}
__device__ __forceinline__ void ldm4t(uint32_t (&r)[4], uint32_t addr) {
    asm volatile("ldmatrix.sync.aligned.m8n8.x4.trans.shared.b16 {%0,%1,%2,%3}, [%4];"
                 : "=r"(r[0]), "=r"(r[1]), "=r"(r[2]), "=r"(r[3]) : "r"(addr));
}

__device__ __forceinline__ uint32_t smem_u32(const void* p) {
    return (uint32_t)__cvta_generic_to_shared(p);
}

__device__ __forceinline__ void cpa(uint32_t dst, const void* src) {
    asm volatile("cp.async.cg.shared.global [%0], [%1], 16;"
                 :: "r"(dst), "l"(src) : "memory");
}
__device__ __forceinline__ void cpa_commit() {
    asm volatile("cp.async.commit_group;" ::: "memory");
}
__device__ __forceinline__ void cpa_wait1() {
    asm volatile("cp.async.wait_group 1;" ::: "memory");
}
__device__ __forceinline__ void cpa_wait0() {
    asm volatile("cp.async.wait_group 0;" ::: "memory");
}

// ---------------------------------------------------------------------------
// pre-pass: fp16 conversions + RoPE table.
// wq folded with 1/sqrt(dk)*log2(e) (exp2-domain softmax).
// ---------------------------------------------------------------------------
__global__ void to_half(const float4* __restrict__ x, const float4* __restrict__ wq,
                        const float4* __restrict__ wk, const float4* __restrict__ wv,
                        const float4* __restrict__ wo, const int* __restrict__ pos)
{
    const int NX = MTOT * D_MODEL / 4;
    const int NW = D_MODEL * D_MODEL / 4;
    const int NR = SEQ * 32;
    const int stride = gridDim.x * blockDim.x;
    uint2* xh = (uint2*)g_xh;
    uint2* wqh = (uint2*)g_wqh;
    uint2* wkh = (uint2*)g_wkh;
    uint2* wvh = (uint2*)g_wvh;
    uint2* woh = (uint2*)g_woh;

    for (int i = blockIdx.x * blockDim.x + threadIdx.x; i < NX; i += stride) {
        float4 v = x[i];
        xh[i] = make_uint2(pack2(v.x, v.y), pack2(v.z, v.w));
    }
    for (int i = blockIdx.x * blockDim.x + threadIdx.x; i < NW; i += stride) {
        float4 a = wq[i];
        wqh[i] = make_uint2(pack2(a.x * QSCALE, a.y * QSCALE),
                            pack2(a.z * QSCALE, a.w * QSCALE));
        float4 b = wk[i];
        wkh[i] = make_uint2(pack2(b.x, b.y), pack2(b.z, b.w));
        float4 c = wv[i];
        wvh[i] = make_uint2(pack2(c.x, c.y), pack2(c.z, c.w));
        float4 d = wo[i];
        woh[i] = make_uint2(pack2(d.x, d.y), pack2(d.z, d.w));
    }
    const float lg = logf(10000.0f);
    for (int i = blockIdx.x * blockDim.x + threadIdx.x; i < NR; i += stride) {
        int s = i >> 5;
        int j = i & 31;
        float invf = expf(-lg * ((float)(2 * j) / (float)D_K));
        float sn, cs;
        sincosf((float)pos[s] * invf, &sn, &cs);
        g_rope[i] = make_float2(cs, sn);
    }
}

// ---------------------------------------------------------------------------
// GEMM: 128x128 block, 4 warps, warp tile 64x64, BK=64, cp.async double-buffer.
// PDLB=true: issue B stage-0 loads BEFORE griddepcontrol.wait (B is
// independent of the preceding grid), A after. Group math: B(G0) + A(G1)
// then loop commit(G2); wait_group 1 drains G0+G1 exactly like before.
// ---------------------------------------------------------------------------
#define GROW 144u
#define GOP (128u * GROW)
#define GSTAGE (2u * GOP)
#define GSMEM (2u * GSTAGE)
#define NKT (D_MODEL / 64)

template<bool PDLB>
__device__ __forceinline__ void gemm_mainloop(
    const __half* __restrict__ A, const __half* __restrict__ B,
    int bm, int bn, uint32_t sbase, float (&acc)[4][8][4])
{
    const int tid = threadIdx.x;
    const int lane = tid & 31;
    const int warp = tid >> 5;
    const int warp_m = warp >> 1;
    const int warp_n = warp & 1;

    const int r0 = tid >> 3;
    const int d = tid & 7;

    const uint4* Au4 = (const uint4*)(A + (size_t)bm * D_MODEL);
    const uint4* Bu4 = (const uint4*)(B + (size_t)bn * D_MODEL);

    const int l = lane;
    const uint32_t a_base =
        (uint32_t)(warp_m * 64 + (l & 7) + 8 * ((l >> 3) & 1)) * GROW +
        ((l >> 4) & 1) * 16u;
    const uint32_t b_base =
        (uint32_t)(warp_n * 64 + (l & 7) + 8 * ((l >> 4) & 1)) * GROW +
        ((l >> 3) & 1) * 16u;

    // prologue: stage 0
    {
        uint32_t as_ = sbase, bs_ = sbase + GOP;
        if (PDLB) {
            // B is independent of the predecessor grid: prefetch before wait
#pragma unroll
            for (int i = 0; i < 8; i++) {
                int row = r0 + 16 * i;
                cpa(bs_ + row * GROW + d * 16, Bu4 + row * 128 + d);
            }
            cpa_commit();
            gdc_wait();
#pragma unroll
            for (int i = 0; i < 8; i++) {
                int row = r0 + 16 * i;
                cpa(as_ + row * GROW + d * 16, Au4 + row * 128 + d);
            }
            cpa_commit();
        } else {
#pragma unroll
            for (int i = 0; i < 8; i++) {
                int row = r0 + 16 * i;
                cpa(as_ + row * GROW + d * 16, Au4 + row * 128 + d);
                cpa(bs_ + row * GROW + d * 16, Bu4 + row * 128 + d);
            }
            cpa_commit();
        }
    }

    for (int kt = 0; kt < NKT; kt++) {
        const uint32_t buf = (uint32_t)(kt & 1);
        if (kt + 1 < NKT) {
            uint32_t as_ = sbase + (buf ^ 1) * GSTAGE;
            uint32_t bs_ = as_ + GOP;
#pragma unroll
            for (int i = 0; i < 8; i++) {
                int row = r0 + 16 * i;
                cpa(as_ + row * GROW + d * 16, Au4 + row * 128 + (kt + 1) * 8 + d);
                cpa(bs_ + row * GROW + d * 16, Bu4 + row * 128 + (kt + 1) * 8 + d);
            }
            cpa_commit();
            cpa_wait1();
        } else {
            cpa_wait0();
        }
        __syncthreads();

        const uint32_t aS = sbase + buf * GSTAGE;
        const uint32_t bS = aS + GOP;
#pragma unroll
        for (int g = 0; g < 4; g++) {
            uint32_t af[4][4], bf[4][4];
#pragma unroll
            for (int mt = 0; mt < 4; mt++)
                ldm4(af[mt], aS + a_base + (uint32_t)mt * 2304u + (uint32_t)g * 32u);
#pragma unroll
            for (int p = 0; p < 4; p++)
                ldm4(bf[p], bS + b_base + (uint32_t)p * 2304u + (uint32_t)g * 32u);
#pragma unroll
            for (int mt = 0; mt < 4; mt++)
#pragma unroll
                for (int nt = 0; nt < 8; nt++)
                    mma_f16(acc[mt][nt], af[mt][0], af[mt][1], af[mt][2], af[mt][3],
                            bf[nt >> 1][(nt & 1) * 2], bf[nt >> 1][(nt & 1) * 2 + 1]);
        }
        __syncthreads();
    }
}

// Fused QKV projection; RoPE via precomputed table.
__global__ __launch_bounds__(128)
void gemm_qkv()
{
    extern __shared__ __align__(16) uint32_t dsm[];
    const uint32_t sbase = smem_u32(dsm);

    const int mat = blockIdx.x >> 3;
    const int bn = (blockIdx.x & 7) * 128;
    const int bm = blockIdx.y * 128;

    const __half* B = (mat == 0) ? g_wqh : (mat == 1) ? g_wkh : g_wvh;
    __half* C = (mat == 0) ? g_qh : (mat == 1) ? g_kh : g_vh;
    const int rope = (mat < 2);

    float acc[4][8][4];
#pragma unroll
    for (int i = 0; i < 4; i++)
#pragma unroll
        for (int j = 0; j < 8; j++)
#pragma unroll
            for (int v = 0; v < 4; v++) acc[i][j][v] = 0.0f;

    gdc_wait();   // all inputs (x_h, weights, rope) come from to_half
    gemm_mainloop<false>(g_xh, B, bm, bn, sbase, acc);

    const int lane = threadIdx.x & 31;
    const int warp = threadIdx.x >> 5;
    const int gid = lane >> 2;
    const int tig = lane & 3;
    const int warp_m = warp >> 1;
    const int warp_n = warp & 1;

    if (rope) {
#pragma unroll
        for (int mt = 0; mt < 4; mt++) {
            int r0 = bm + warp_m * 64 + mt * 16 + gid;
            int s0 = r0 & (SEQ - 1);
            int s1 = (r0 + 8) & (SEQ - 1);
#pragma unroll
            for (int nt = 0; nt < 8; nt++) {
                int c = bn + warp_n * 64 + nt * 8 + 2 * tig;
                int j = (c & (D_K - 1)) >> 1;
                float2 r0v = g_rope[s0 * 32 + j];
                float2 r1v = g_rope[s1 * 32 + j];
                float v0 = acc[mt][nt][0], v1 = acc[mt][nt][1];
                float w0 = acc[mt][nt][2], w1 = acc[mt][nt][3];
                *(uint32_t*)&C[(size_t)r0 * D_MODEL + c] =
                    pack2(v0 * r0v.x - v1 * r0v.y, v0 * r0v.y + v1 * r0v.x);
                *(uint32_t*)&C[(size_t)(r0 + 8) * D_MODEL + c] =
                    pack2(w0 * r1v.x - w1 * r1v.y, w0 * r1v.y + w1 * r1v.x);
            }
        }
    } else {
#pragma unroll
        for (int mt = 0; mt < 4; mt++) {
            int r0 = bm + warp_m * 64 + mt * 16 + gid;
#pragma unroll
            for (int nt = 0; nt < 8; nt++) {
                int c = bn + warp_n * 64 + nt * 8 + 2 * tig;
                *(uint32_t*)&C[(size_t)r0 * D_MODEL + c] =
                    pack2(acc[mt][nt][0], acc[mt][nt][1]);
                *(uint32_t*)&C[(size_t)(r0 + 8) * D_MODEL + c] =
                    pack2(acc[mt][nt][2], acc[mt][nt][3]);
            }
        }
    }
}

// Output projection: fp16 A (g_oh) x fp16 W -> fp32 out.
// PDL: weight tile prefetched before the dependency wait (see mainloop).
__global__ __launch_bounds__(128)
void gemm_wo(float* __restrict__ C)
{
    extern __shared__ __align__(16) uint32_t dsm[];
    const uint32_t sbase = smem_u32(dsm);

    const int bn = blockIdx.x * 128;
    const int bm = blockIdx.y * 128;

    float acc[4][8][4];
#pragma unroll
    for (int i = 0; i < 4; i++)
#pragma unroll
        for (int j = 0; j < 8; j++)
#pragma unroll
            for (int v = 0; v < 4; v++) acc[i][j][v] = 0.0f;

    gemm_mainloop<true>(g_oh, g_woh, bm, bn, sbase, acc);

    const int lane = threadIdx.x & 31;
    const int warp = threadIdx.x >> 5;
    const int gid = lane >> 2;
    const int tig = lane & 3;
    const int warp_m = warp >> 1;
    const int warp_n = warp & 1;

#pragma unroll
    for (int mt = 0; mt < 4; mt++) {
        int r0 = bm + warp_m * 64 + mt * 16 + gid;
#pragma unroll
        for (int nt = 0; nt < 8; nt++) {
            int c = bn + warp_n * 64 + nt * 8 + 2 * tig;
            *(float2*)&C[(size_t)r0 * D_MODEL + c] =
                make_float2(acc[mt][nt][0], acc[mt][nt][1]);
            *(float2*)&C[(size_t)(r0 + 8) * D_MODEL + c] =
                make_float2(acc[mt][nt][2], acc[mt][nt][3]);
        }
    }
}

// ---------------------------------------------------------------------------
// Flash attention: Br=128 (4 warps x 32 q), KV tiles of 64 keys in 3-stage
// cp.async ring (one syncthreads per tile), exp2-domain softmax.
// ---------------------------------------------------------------------------
#define AST 18432u
#define ASMEM (3u * AST)

__global__ __launch_bounds__(128)
void attn_f16()
{
    extern __shared__ __align__(16) uint32_t asm_[];
    const uint32_t sb = smem_u32(asm_);

    const int tid = threadIdx.x;
    const int warp = tid >> 5;
    const int lane = tid & 31;
    const int gid = lane >> 2;
    const int tig = lane & 3;

    const int qt = (int)gridDim.x - 1 - (int)blockIdx.x;  // heavy blocks first
    const int bh = blockIdx.y;
    const int q0 = qt * 128;
    const size_t base = (size_t)(bh >> 4) * SEQ * D_MODEL + (size_t)(bh & 15) * D_K;

    const int qw = q0 + warp * 32;
    const int rowmax = qw + 31;

    const int l = lane;
    const uint32_t k_lane =
        (uint32_t)(((l & 7) + 8 * ((l >> 4) & 1)) * 36 + 4 * ((l >> 3) & 1)) * 4;
    const uint32_t v_lane = 9216u +
        (uint32_t)(((l & 7) + 8 * ((l >> 3) & 1)) * 36 + 4 * ((l >> 4) & 1)) * 4;

    gdc_wait();   // Q/K/V all come from gemm_qkv

    uint32_t qa[4][8];
#pragma unroll
    for (int ma = 0; ma < 2; ma++) {
        const __half* Qr0 = g_qh + base + (size_t)(qw + ma * 16 + gid) * D_MODEL;
        const __half* Qr1 = Qr0 + 8 * D_MODEL;
#pragma unroll
        for (int ks = 0; ks < 4; ks++) {
            qa[ks][ma * 4 + 0] = *(const uint32_t*)&Qr0[ks * 16 + 2 * tig];
            qa[ks][ma * 4 + 1] = *(const uint32_t*)&Qr1[ks * 16 + 2 * tig];
            qa[ks][ma * 4 + 2] = *(const uint32_t*)&Qr0[ks * 16 + 2 * tig + 8];
            qa[ks][ma * 4 + 3] = *(const uint32_t*)&Qr1[ks * 16 + 2 * tig + 8];
        }
    }

    float of[2][8][4];
#pragma unroll
    for (int ma = 0; ma < 2; ma++)
#pragma unroll
        for (int i = 0; i < 8; i++)
#pragma unroll
            for (int j = 0; j < 4; j++) of[ma][i][j] = 0.0f;
    float mm[2][2] = {{-1e30f, -1e30f}, {-1e30f, -1e30f}};
    float ll[2][2] = {{0.0f, 0.0f}, {0.0f, 0.0f}};

    const int kr = tid >> 3;
    const int d8 = tid & 7;

    const int nkb = (q0 + 128) / 64;

    {
        const uint4* Kt = (const uint4*)(g_kh + base) + (size_t)kr * 128 + d8;
        const uint4* Vt = (const uint4*)(g_vh + base) + (size_t)kr * 128 + d8;
        uint32_t kd = sb + kr * 144 + d8 * 16;
#pragma unroll
        for (int i = 0; i < 4; i++) {
            cpa(kd + i * 2304u, Kt + (size_t)i * 2048);
            cpa(kd + 9216u + i * 2304u, Vt + (size_t)i * 2048);
        }
        cpa_commit();
    }

    int cs = 0;
    for (int kb = 0; kb < nkb; kb++) {
        const int k0 = kb * 64;
        if (kb + 1 < nkb) {
            int ns = cs + 1; if (ns == 3) ns = 0;
            const uint4* Kt = (const uint4*)(g_kh + base) +
                              ((size_t)(k0 + 64 + kr)) * 128 + d8;
            const uint4* Vt = (const uint4*)(g_vh + base) +
                              ((size_t)(k0 + 64 + kr)) * 128 + d8;
            uint32_t kd = sb + ns * AST + kr * 144 + d8 * 16;
#pragma unroll
            for (int i = 0; i < 4; i++) {
                cpa(kd + i * 2304u, Kt + (size_t)i * 2048);
                cpa(kd + 9216u + i * 2304u, Vt + (size_t)i * 2048);
            }
            cpa_commit();
            cpa_wait1();
        } else {
            cpa_wait0();
        }
        __syncthreads();

        const uint32_t stg = sb + cs * AST;
#pragma unroll
        for (int h = 0; h < 2; h++) {
            const int k0h = k0 + h * 32;
            if (k0h > rowmax) break;
            const uint32_t hoff = (uint32_t)h * 4608u;

            float sc[2][4][4];
#pragma unroll
            for (int ma = 0; ma < 2; ma++)
#pragma unroll
                for (int nt = 0; nt < 4; nt++)
#pragma unroll
                    for (int v = 0; v < 4; v++) sc[ma][nt][v] = 0.0f;
#pragma unroll
            for (int ks = 0; ks < 4; ks++) {
                uint32_t kb0[4], kb1[4];
                ldm4(kb0, stg + k_lane + hoff + (uint32_t)ks * 32u);
                ldm4(kb1, stg + k_lane + hoff + 2304u + (uint32_t)ks * 32u);
#pragma unroll
                for (int ma = 0; ma < 2; ma++) {
                    mma_f16(sc[ma][0], qa[ks][ma*4+0], qa[ks][ma*4+1],
                            qa[ks][ma*4+2], qa[ks][ma*4+3], kb0[0], kb0[1]);
                    mma_f16(sc[ma][1], qa[ks][ma*4+0], qa[ks][ma*4+1],
                            qa[ks][ma*4+2], qa[ks][ma*4+3], kb0[2], kb0[3]);
                    mma_f16(sc[ma][2], qa[ks][ma*4+0], qa[ks][ma*4+1],
                            qa[ks][ma*4+2], qa[ks][ma*4+3], kb1[0], kb1[1]);
                    mma_f16(sc[ma][3], qa[ks][ma*4+0], qa[ks][ma*4+1],
                            qa[ks][ma*4+2], qa[ks][ma*4+3], kb1[2], kb1[3]);
                }
            }

            if (k0h + 31 > qw) {
#pragma unroll
                for (int ma = 0; ma < 2; ma++) {
                    int r0g = qw + ma * 16 + gid;
                    int r1g = r0g + 8;
#pragma unroll
                    for (int nt = 0; nt < 4; nt++) {
                        int c = k0h + nt * 8 + 2 * tig;
                        if (c > r0g)     sc[ma][nt][0] = -1e30f;
                        if (c + 1 > r0g) sc[ma][nt][1] = -1e30f;
                        if (c > r1g)     sc[ma][nt][2] = -1e30f;
                        if (c + 1 > r1g) sc[ma][nt][3] = -1e30f;
                    }
                }
            }

            uint32_t pa[2][2][4];
#pragma unroll
            for (int ma = 0; ma < 2; ma++) {
                float mx0 = sc[ma][0][0], mx1 = sc[ma][0][2];
#pragma unroll
                for (int nt = 0; nt < 4; nt++) {
                    mx0 = fmaxf(mx0, fmaxf(sc[ma][nt][0], sc[ma][nt][1]));
                    mx1 = fmaxf(mx1, fmaxf(sc[ma][nt][2], sc[ma][nt][3]));
                }
                mx0 = fmaxf(mx0, __shfl_xor_sync(0xffffffffu, mx0, 1));
                mx0 = fmaxf(mx0, __shfl_xor_sync(0xffffffffu, mx0, 2));
                mx1 = fmaxf(mx1, __shfl_xor_sync(0xffffffffu, mx1, 1));
                mx1 = fmaxf(mx1, __shfl_xor_sync(0xffffffffu, mx1, 2));

                float mn0 = fmaxf(mm[ma][0], mx0);
                float mn1 = fmaxf(mm[ma][1], mx1);
                float al0 = ex2(mm[ma][0] - mn0);
                float al1 = ex2(mm[ma][1] - mn1);
                mm[ma][0] = mn0; mm[ma][1] = mn1;

                float sum0 = 0.0f, sum1 = 0.0f;
#pragma unroll
                for (int nt = 0; nt < 4; nt++) {
                    sc[ma][nt][0] = ex2(sc[ma][nt][0] - mn0);
                    sc[ma][nt][1] = ex2(sc[ma][nt][1] - mn0);
                    sc[ma][nt][2] = ex2(sc[ma][nt][2] - mn1);
                    sc[ma][nt][3] = ex2(sc[ma][nt][3] - mn1);
                    sum0 += sc[ma][nt][0] + sc[ma][nt][1];
                    sum1 += sc[ma][nt][2] + sc[ma][nt][3];
                }
                sum0 += __shfl_xor_sync(0xffffffffu, sum0, 1);
                sum0 += __shfl_xor_sync(0xffffffffu, sum0, 2);
                sum1 += __shfl_xor_sync(0xffffffffu, sum1, 1);
                sum1 += __shfl_xor_sync(0xffffffffu, sum1, 2);
                ll[ma][0] = ll[ma][0] * al0 + sum0;
                ll[ma][1] = ll[ma][1] * al1 + sum1;

#pragma unroll
                for (int nt = 0; nt < 8; nt++) {
                    of[ma][nt][0] *= al0; of[ma][nt][1] *= al0;
                    of[ma][nt][2] *= al1; of[ma][nt][3] *= al1;
                }

#pragma unroll
                for (int s = 0; s < 2; s++) {
                    pa[ma][s][0] = pack2(sc[ma][2*s][0], sc[ma][2*s][1]);
                    pa[ma][s][1] = pack2(sc[ma][2*s][2], sc[ma][2*s][3]);
                    pa[ma][s][2] = pack2(sc[ma][2*s+1][0], sc[ma][2*s+1][1]);
                    pa[ma][s][3] = pack2(sc[ma][2*s+1][2], sc[ma][2*s+1][3]);
                }
            }

#pragma unroll
            for (int s = 0; s < 2; s++) {
#pragma unroll
                for (int dp = 0; dp < 4; dp++) {
                    uint32_t vb[4];
                    ldm4t(vb, stg + v_lane + hoff + (uint32_t)s * 2304u +
                              (uint32_t)dp * 32u);
#pragma unroll
                    for (int ma = 0; ma < 2; ma++) {
                        mma_f16(of[ma][dp * 2], pa[ma][s][0], pa[ma][s][1],
                                pa[ma][s][2], pa[ma][s][3], vb[0], vb[1]);
                        mma_f16(of[ma][dp * 2 + 1], pa[ma][s][0], pa[ma][s][1],
                                pa[ma][s][2], pa[ma][s][3], vb[2], vb[3]);
                    }
                }
            }
        }
        cs++; if (cs == 3) cs = 0;
    }

#pragma unroll
    for (int ma = 0; ma < 2; ma++) {
        float inv0 = 1.0f / ll[ma][0];
        float inv1 = 1.0f / ll[ma][1];
        __half* O0 = g_oh + base + (size_t)(qw + ma * 16 + gid) * D_MODEL;
        __half* O1 = O0 + 8 * D_MODEL;
#pragma unroll
        for (int nt = 0; nt < 8; nt++) {
            int c = nt * 8 + 2 * tig;
            *(uint32_t*)&O0[c] = pack2(of[ma][nt][0] * inv0, of[ma][nt][1] * inv0);
            *(uint32_t*)&O1[c] = pack2(of[ma][nt][2] * inv1, of[ma][nt][3] * inv1);
        }
    }
}

// ---------------------------------------------------------------------------
// launcher: in-stream PDL chain (no events, no extra streams).
// ---------------------------------------------------------------------------
extern "C" void kernel_launch(void* const* d_in, const int* in_sizes, int n_in,
                              void* d_out, int out_size)
{
    const float* x  = (const float*)d_in[0];
    const float* wq = (const float*)d_in[1];
    const float* wk = (const float*)d_in[2];
    const float* wv = (const float*)d_in[3];
    const float* wo = (const float*)d_in[4];
    const int* tok  = (const int*)d_in[5];
    float* out = (float*)d_out;

    cudaFuncSetAttribute(gemm_qkv, cudaFuncAttributeMaxDynamicSharedMemorySize, GSMEM);
    cudaFuncSetAttribute(gemm_wo, cudaFuncAttributeMaxDynamicSharedMemorySize, GSMEM);
    cudaFuncSetAttribute(attn_f16, cudaFuncAttributeMaxDynamicSharedMemorySize, ASMEM);

    to_half<<<2048, 256>>>((const float4*)x, (const float4*)wq,
                           (const float4*)wk, (const float4*)wv,
                           (const float4*)wo, tok);

    cudaLaunchAttribute pa[1];
    pa[0].id = cudaLaunchAttributeProgrammaticStreamSerialization;
    pa[0].val.programmaticStreamSerializationAllowed = 1;

    {
        cudaLaunchConfig_t cfg = {};
        cfg.gridDim = dim3(24, MTOT / 128);   // (24, 64) fused QKV
        cfg.blockDim = dim3(128);
        cfg.dynamicSmemBytes = GSMEM;
        cfg.stream = 0;
        cfg.attrs = pa;
        cfg.numAttrs = 1;
        cudaLaunchKernelEx(&cfg, gemm_qkv);
    }
    {
        cudaLaunchConfig_t cfg = {};
        cfg.gridDim = dim3(SEQ / 128, BATCH * NUM_HEADS);   // (16, 64)
        cfg.blockDim = dim3(128);
        cfg.dynamicSmemBytes = ASMEM;
        cfg.stream = 0;
        cfg.attrs = pa;
        cfg.numAttrs = 1;
        cudaLaunchKernelEx(&cfg, attn_f16);
    }
    {
        cudaLaunchConfig_t cfg = {};
        cfg.gridDim = dim3(D_MODEL / 128, MTOT / 128);   // (8, 64)
        cfg.blockDim = dim3(128);
        cfg.dynamicSmemBytes = GSMEM;
        cfg.stream = 0;
        cfg.attrs = pa;
        cfg.numAttrs = 1;
        cudaLaunchKernelEx(&cfg, gemm_wo, out);
    }
}

// round 15
// speedup vs baseline: 1.1438x; 1.0027x over previous
#include <cuda_runtime.h>
#include <cuda_fp16.h>
#include <math.h>
#include <stdint.h>

#define D_MODEL 1024
#define NUM_HEADS 16
#define SEQ 2048
#define BATCH 4
#define D_K 64
#define MTOT (BATCH * SEQ)   // 8192

// fp16 scratch (static device globals; no runtime allocation allowed)
__device__ __align__(16) __half g_xh[MTOT * D_MODEL];
__device__ __align__(16) __half g_qh[MTOT * D_MODEL];
__device__ __align__(16) __half g_kh[MTOT * D_MODEL];
__device__ __align__(16) __half g_vh[MTOT * D_MODEL];
__device__ __align__(16) __half g_oh[MTOT * D_MODEL];
__device__ __align__(16) __half g_wqh[D_MODEL * D_MODEL];
__device__ __align__(16) __half g_wkh[D_MODEL * D_MODEL];
__device__ __align__(16) __half g_wvh[D_MODEL * D_MODEL];
__device__ __align__(16) __half g_woh[D_MODEL * D_MODEL];
__device__ __align__(16) float2 g_rope[SEQ * 32];   // (cos, sin) per (pos, j)

#define QSCALE (0.125f * 1.4426950408889634f)   // 1/sqrt(dk) * log2(e)

// ---------------------------------------------------------------------------
// helpers
// ---------------------------------------------------------------------------
__device__ __forceinline__ uint32_t pack2(float lo, float hi) {
    uint32_t r;
    asm("cvt.rn.f16x2.f32 %0, %1, %2;" : "=r"(r) : "f"(hi), "f"(lo));
    return r;
}

__device__ __forceinline__ float ex2(float x) {
    float r;
    asm("ex2.approx.ftz.f32 %0, %1;" : "=f"(r) : "f"(x));
    return r;
}

// PDL: wait for the preceding grid (only needed before touching its outputs)
__device__ __forceinline__ void gdc_wait() {
    asm volatile("griddepcontrol.wait;" ::: "memory");
}

__device__ __forceinline__ void mma_f16(float c[4], uint32_t a0, uint32_t a1,
                                        uint32_t a2, uint32_t a3,
                                        uint32_t b0, uint32_t b1) {
    asm volatile(
        "mma.sync.aligned.m16n8k16.row.col.f32.f16.f16.f32 "
        "{%0,%1,%2,%3},{%4,%5,%6,%7},{%8,%9},{%0,%1,%2,%3};"
        : "+f"(c[0]), "+f"(c[1]), "+f"(c[2]), "+f"(c[3])
        : "r"(a0), "r"(a1), "r"(a2), "r"(a3), "r"(b0), "r"(b1));
}

__device__ __forceinline__ void ldm4(uint32_t (&r)[4], uint32_t addr) {
    asm volatile("ldmatrix.sync.aligned.m8n8.x4.shared.b16 {%0,%1,%2,%3}, [%4];"
                 : "=r"(r[0]), "=r"(r[1]), "=r"(r[2]), "=r"(r[3]) : "r"(addr));
}
__device__ __forceinline__ void ldm4t(uint32_t (&r)[4], uint32_t addr) {
    asm volatile("ldmatrix.sync.aligned.m8n8.x4.trans.shared.b16 {%0,%1,%2,%3}, [%4];"
                 : "=r"(r[0]), "=r"(r[1]), "=r"(r[2]), "=r"(r[3]) : "r"(addr));
}

__device__ __forceinline__ uint32_t smem_u32(const void* p) {
    return (uint32_t)__cvta_generic_to_shared(p);
}

__device__ __forceinline__ void cpa(uint32_t dst, const void* src) {
    asm volatile("cp.async.cg.shared.global [%0], [%1], 16;"
                 :: "r"(dst), "l"(src) : "memory");
}
__device__ __forceinline__ void cpa_commit() {
    asm volatile("cp.async.commit_group;" ::: "memory");
}
__device__ __forceinline__ void cpa_wait1() {
    asm volatile("cp.async.wait_group 1;" ::: "memory");
}
__device__ __forceinline__ void cpa_wait0() {
    asm volatile("cp.async.wait_group 0;" ::: "memory");
}

// ---------------------------------------------------------------------------
// pre-pass: fp16 conversions + RoPE table.
// wq folded with 1/sqrt(dk)*log2(e) (exp2-domain softmax).
// ---------------------------------------------------------------------------
__global__ void to_half(const float4* __restrict__ x, const float4* __restrict__ wq,
                        const float4* __restrict__ wk, const float4* __restrict__ wv,
                        const float4* __restrict__ wo, const int* __restrict__ pos)
{
    const int NX = MTOT * D_MODEL / 4;
    const int NW = D_MODEL * D_MODEL / 4;
    const int NR = SEQ * 32;
    const int stride = gridDim.x * blockDim.x;
    uint2* xh = (uint2*)g_xh;
    uint2* wqh = (uint2*)g_wqh;
    uint2* wkh = (uint2*)g_wkh;
    uint2* wvh = (uint2*)g_wvh;
    uint2* woh = (uint2*)g_woh;

    for (int i = blockIdx.x * blockDim.x + threadIdx.x; i < NX; i += stride) {
        float4 v = x[i];
        xh[i] = make_uint2(pack2(v.x, v.y), pack2(v.z, v.w));
    }
    for (int i = blockIdx.x * blockDim.x + threadIdx.x; i < NW; i += stride) {
        float4 a = wq[i];
        wqh[i] = make_uint2(pack2(a.x * QSCALE, a.y * QSCALE),
                            pack2(a.z * QSCALE, a.w * QSCALE));
        float4 b = wk[i];
        wkh[i] = make_uint2(pack2(b.x, b.y), pack2(b.z, b.w));
        float4 c = wv[i];
        wvh[i] = make_uint2(pack2(c.x, c.y), pack2(c.z, c.w));
        float4 d = wo[i];
        woh[i] = make_uint2(pack2(d.x, d.y), pack2(d.z, d.w));
    }
    const float lg = logf(10000.0f);
    for (int i = blockIdx.x * blockDim.x + threadIdx.x; i < NR; i += stride) {
        int s = i >> 5;
        int j = i & 31;
        float invf = expf(-lg * ((float)(2 * j) / (float)D_K));
        float sn, cs;
        sincosf((float)pos[s] * invf, &sn, &cs);
        g_rope[i] = make_float2(cs, sn);
    }
}

// ---------------------------------------------------------------------------
// GEMM: 128x128 block, 4 warps, warp tile 64x64, BK=64, cp.async double-buffer.
// PDLB=true: issue B stage-0 loads BEFORE griddepcontrol.wait (B is
// independent of the preceding grid), A after. Group math: B(G0) + A(G1)
// then loop commit(G2); wait_group 1 drains G0+G1 exactly like before.
// ---------------------------------------------------------------------------
#define GROW 144u
#define GOP (128u * GROW)
#define GSTAGE (2u * GOP)
#define GSMEM (2u * GSTAGE)
#define NKT (D_MODEL / 64)

template<bool PDLB>
__device__ __forceinline__ void gemm_mainloop(
    const __half* __restrict__ A, const __half* __restrict__ B,
    int bm, int bn, uint32_t sbase, float (&acc)[4][8][4])
{
    const int tid = threadIdx.x;
    const int lane = tid & 31;
    const int warp = tid >> 5;
    const int warp_m = warp >> 1;
    const int warp_n = warp & 1;

    const int r0 = tid >> 3;
    const int d = tid & 7;

    const uint4* Au4 = (const uint4*)(A + (size_t)bm * D_MODEL);
    const uint4* Bu4 = (const uint4*)(B + (size_t)bn * D_MODEL);

    const int l = lane;
    const uint32_t a_base =
        (uint32_t)(warp_m * 64 + (l & 7) + 8 * ((l >> 3) & 1)) * GROW +
        ((l >> 4) & 1) * 16u;
    const uint32_t b_base =
        (uint32_t)(warp_n * 64 + (l & 7) + 8 * ((l >> 4) & 1)) * GROW +
        ((l >> 3) & 1) * 16u;

    // prologue: stage 0
    {
        uint32_t as_ = sbase, bs_ = sbase + GOP;
        if (PDLB) {
            // B is independent of the predecessor grid: prefetch before wait
#pragma unroll
            for (int i = 0; i < 8; i++) {
                int row = r0 + 16 * i;
                cpa(bs_ + row * GROW + d * 16, Bu4 + row * 128 + d);
            }
            cpa_commit();
            gdc_wait();
#pragma unroll
            for (int i = 0; i < 8; i++) {
                int row = r0 + 16 * i;
                cpa(as_ + row * GROW + d * 16, Au4 + row * 128 + d);
            }
            cpa_commit();
        } else {
#pragma unroll
            for (int i = 0; i < 8; i++) {
                int row = r0 + 16 * i;
                cpa(as_ + row * GROW + d * 16, Au4 + row * 128 + d);
                cpa(bs_ + row * GROW + d * 16, Bu4 + row * 128 + d);
            }
            cpa_commit();
        }
    }

    for (int kt = 0; kt < NKT; kt++) {
        const uint32_t buf = (uint32_t)(kt & 1);
        if (kt + 1 < NKT) {
            uint32_t as_ = sbase + (buf ^ 1) * GSTAGE;
            uint32_t bs_ = as_ + GOP;
#pragma unroll
            for (int i = 0; i < 8; i++) {
                int row = r0 + 16 * i;
                cpa(as_ + row * GROW + d * 16, Au4 + row * 128 + (kt + 1) * 8 + d);
                cpa(bs_ + row * GROW + d * 16, Bu4 + row * 128 + (kt + 1) * 8 + d);
            }
            cpa_commit();
            cpa_wait1();
        } else {
            cpa_wait0();
        }
        __syncthreads();

        const uint32_t aS = sbase + buf * GSTAGE;
        const uint32_t bS = aS + GOP;
#pragma unroll
        for (int g = 0; g < 4; g++) {
            uint32_t af[4][4], bf[4][4];
#pragma unroll
            for (int mt = 0; mt < 4; mt++)
                ldm4(af[mt], aS + a_base + (uint32_t)mt * 2304u + (uint32_t)g * 32u);
#pragma unroll
            for (int p = 0; p < 4; p++)
                ldm4(bf[p], bS + b_base + (uint32_t)p * 2304u + (uint32_t)g * 32u);
#pragma unroll
            for (int mt = 0; mt < 4; mt++)
#pragma unroll
                for (int nt = 0; nt < 8; nt++)
                    mma_f16(acc[mt][nt], af[mt][0], af[mt][1], af[mt][2], af[mt][3],
                            bf[nt >> 1][(nt & 1) * 2], bf[nt >> 1][(nt & 1) * 2 + 1]);
        }
        __syncthreads();
    }
}

// Fused QKV projection; RoPE via precomputed table.
__global__ __launch_bounds__(128)
void gemm_qkv()
{
    extern __shared__ __align__(16) uint32_t dsm[];
    const uint32_t sbase = smem_u32(dsm);

    const int mat = blockIdx.x >> 3;
    const int bn = (blockIdx.x & 7) * 128;
    const int bm = blockIdx.y * 128;

    const __half* B = (mat == 0) ? g_wqh : (mat == 1) ? g_wkh : g_wvh;
    __half* C = (mat == 0) ? g_qh : (mat == 1) ? g_kh : g_vh;
    const int rope = (mat < 2);

    float acc[4][8][4];
#pragma unroll
    for (int i = 0; i < 4; i++)
#pragma unroll
        for (int j = 0; j < 8; j++)
#pragma unroll
            for (int v = 0; v < 4; v++) acc[i][j][v] = 0.0f;

    gdc_wait();   // all inputs (x_h, weights, rope) come from to_half
    gemm_mainloop<false>(g_xh, B, bm, bn, sbase, acc);

    const int lane = threadIdx.x & 31;
    const int warp = threadIdx.x >> 5;
    const int gid = lane >> 2;
    const int tig = lane & 3;
    const int warp_m = warp >> 1;
    const int warp_n = warp & 1;

    if (rope) {
#pragma unroll
        for (int mt = 0; mt < 4; mt++) {
            int r0 = bm + warp_m * 64 + mt * 16 + gid;
            int s0 = r0 & (SEQ - 1);
            int s1 = (r0 + 8) & (SEQ - 1);
#pragma unroll
            for (int nt = 0; nt < 8; nt++) {
                int c = bn + warp_n * 64 + nt * 8 + 2 * tig;
                int j = (c & (D_K - 1)) >> 1;
                float2 r0v = g_rope[s0 * 32 + j];
                float2 r1v = g_rope[s1 * 32 + j];
                float v0 = acc[mt][nt][0], v1 = acc[mt][nt][1];
                float w0 = acc[mt][nt][2], w1 = acc[mt][nt][3];
                *(uint32_t*)&C[(size_t)r0 * D_MODEL + c] =
                    pack2(v0 * r0v.x - v1 * r0v.y, v0 * r0v.y + v1 * r0v.x);
                *(uint32_t*)&C[(size_t)(r0 + 8) * D_MODEL + c] =
                    pack2(w0 * r1v.x - w1 * r1v.y, w0 * r1v.y + w1 * r1v.x);
            }
        }
    } else {
#pragma unroll
        for (int mt = 0; mt < 4; mt++) {
            int r0 = bm + warp_m * 64 + mt * 16 + gid;
#pragma unroll
            for (int nt = 0; nt < 8; nt++) {
                int c = bn + warp_n * 64 + nt * 8 + 2 * tig;
                *(uint32_t*)&C[(size_t)r0 * D_MODEL + c] =
                    pack2(acc[mt][nt][0], acc[mt][nt][1]);
                *(uint32_t*)&C[(size_t)(r0 + 8) * D_MODEL + c] =
                    pack2(acc[mt][nt][2], acc[mt][nt][3]);
            }
        }
    }
}

// Output projection: fp16 A (g_oh) x fp16 W -> fp32 out.
// PDL: weight tile prefetched before the dependency wait (see mainloop).
__global__ __launch_bounds__(128)
void gemm_wo(float* __restrict__ C)
{
    extern __shared__ __align__(16) uint32_t dsm[];
    const uint32_t sbase = smem_u32(dsm);

    const int bn = blockIdx.x * 128;
    const int bm = blockIdx.y * 128;

    float acc[4][8][4];
#pragma unroll
    for (int i = 0; i < 4; i++)
#pragma unroll
        for (int j = 0; j < 8; j++)
#pragma unroll
            for (int v = 0; v < 4; v++) acc[i][j][v] = 0.0f;

    gemm_mainloop<true>(g_oh, g_woh, bm, bn, sbase, acc);

    const int lane = threadIdx.x & 31;
    const int warp = threadIdx.x >> 5;
    const int gid = lane >> 2;
    const int tig = lane & 3;
    const int warp_m = warp >> 1;
    const int warp_n = warp & 1;

#pragma unroll
    for (int mt = 0; mt < 4; mt++) {
        int r0 = bm + warp_m * 64 + mt * 16 + gid;
#pragma unroll
        for (int nt = 0; nt < 8; nt++) {
            int c = bn + warp_n * 64 + nt * 8 + 2 * tig;
            *(float2*)&C[(size_t)r0 * D_MODEL + c] =
                make_float2(acc[mt][nt][0], acc[mt][nt][1]);
            *(float2*)&C[(size_t)(r0 + 8) * D_MODEL + c] =
                make_float2(acc[mt][nt][2], acc[mt][nt][3]);
        }
    }
}

// ---------------------------------------------------------------------------
// Flash attention: Br=128 (4 warps x 32 q), KV tiles of 64 keys in 3-stage
// cp.async ring (one syncthreads per tile), exp2-domain softmax.
// ---------------------------------------------------------------------------
#define AST 18432u
#define ASMEM (3u * AST)

__global__ __launch_bounds__(128)
void attn_f16()
{
    extern __shared__ __align__(16) uint32_t asm_[];
    const uint32_t sb = smem_u32(asm_);

    const int tid = threadIdx.x;
    const int warp = tid >> 5;
    const int lane = tid & 31;
    const int gid = lane >> 2;
    const int tig = lane & 3;

    const int qt = (int)gridDim.x - 1 - (int)blockIdx.x;  // heavy blocks first
    const int bh = blockIdx.y;
    const int q0 = qt * 128;
    const size_t base = (size_t)(bh >> 4) * SEQ * D_MODEL + (size_t)(bh & 15) * D_K;

    const int qw = q0 + warp * 32;
    const int rowmax = qw + 31;

    const int l = lane;
    const uint32_t k_lane =
        (uint32_t)(((l & 7) + 8 * ((l >> 4) & 1)) * 36 + 4 * ((l >> 3) & 1)) * 4;
    const uint32_t v_lane = 9216u +
        (uint32_t)(((l & 7) + 8 * ((l >> 3) & 1)) * 36 + 4 * ((l >> 4) & 1)) * 4;

    gdc_wait();   // Q/K/V all come from gemm_qkv

    uint32_t qa[4][8];
#pragma unroll
    for (int ma = 0; ma < 2; ma++) {
        const __half* Qr0 = g_qh + base + (size_t)(qw + ma * 16 + gid) * D_MODEL;
        const __half* Qr1 = Qr0 + 8 * D_MODEL;
#pragma unroll
        for (int ks = 0; ks < 4; ks++) {
            qa[ks][ma * 4 + 0] = *(const uint32_t*)&Qr0[ks * 16 + 2 * tig];
            qa[ks][ma * 4 + 1] = *(const uint32_t*)&Qr1[ks * 16 + 2 * tig];
            qa[ks][ma * 4 + 2] = *(const uint32_t*)&Qr0[ks * 16 + 2 * tig + 8];
            qa[ks][ma * 4 + 3] = *(const uint32_t*)&Qr1[ks * 16 + 2 * tig + 8];
        }
    }

    float of[2][8][4];
#pragma unroll
    for (int ma = 0; ma < 2; ma++)
#pragma unroll
        for (int i = 0; i < 8; i++)
#pragma unroll
            for (int j = 0; j < 4; j++) of[ma][i][j] = 0.0f;
    float mm[2][2] = {{-1e30f, -1e30f}, {-1e30f, -1e30f}};
    float ll[2][2] = {{0.0f, 0.0f}, {0.0f, 0.0f}};

    const int kr = tid >> 3;
    const int d8 = tid & 7;

    const int nkb = (q0 + 128) / 64;

    {
        const uint4* Kt = (const uint4*)(g_kh + base) + (size_t)kr * 128 + d8;
        const uint4* Vt = (const uint4*)(g_vh + base) + (size_t)kr * 128 + d8;
        uint32_t kd = sb + kr * 144 + d8 * 16;
#pragma unroll
        for (int i = 0; i < 4; i++) {
            cpa(kd + i * 2304u, Kt + (size_t)i * 2048);
            cpa(kd + 9216u + i * 2304u, Vt + (size_t)i * 2048);
        }
        cpa_commit();
    }

    int cs = 0;
    for (int kb = 0; kb < nkb; kb++) {
        const int k0 = kb * 64;
        if (kb + 1 < nkb) {
            int ns = cs + 1; if (ns == 3) ns = 0;
            const uint4* Kt = (const uint4*)(g_kh + base) +
                              ((size_t)(k0 + 64 + kr)) * 128 + d8;
            const uint4* Vt = (const uint4*)(g_vh + base) +
                              ((size_t)(k0 + 64 + kr)) * 128 + d8;
            uint32_t kd = sb + ns * AST + kr * 144 + d8 * 16;
#pragma unroll
            for (int i = 0; i < 4; i++) {
                cpa(kd + i * 2304u, Kt + (size_t)i * 2048);
                cpa(kd + 9216u + i * 2304u, Vt + (size_t)i * 2048);
            }
            cpa_commit();
            cpa_wait1();
        } else {
            cpa_wait0();
        }
        __syncthreads();

        const uint32_t stg = sb + cs * AST;
#pragma unroll
        for (int h = 0; h < 2; h++) {
            const int k0h = k0 + h * 32;
            if (k0h > rowmax) break;
            const uint32_t hoff = (uint32_t)h * 4608u;

            float sc[2][4][4];
#pragma unroll
            for (int ma = 0; ma < 2; ma++)
#pragma unroll
                for (int nt = 0; nt < 4; nt++)
#pragma unroll
                    for (int v = 0; v < 4; v++) sc[ma][nt][v] = 0.0f;
#pragma unroll
            for (int ks = 0; ks < 4; ks++) {
                uint32_t kb0[4], kb1[4];
                ldm4(kb0, stg + k_lane + hoff + (uint32_t)ks * 32u);
                ldm4(kb1, stg + k_lane + hoff + 2304u + (uint32_t)ks * 32u);
#pragma unroll
                for (int ma = 0; ma < 2; ma++) {
                    mma_f16(sc[ma][0], qa[ks][ma*4+0], qa[ks][ma*4+1],
                            qa[ks][ma*4+2], qa[ks][ma*4+3], kb0[0], kb0[1]);
                    mma_f16(sc[ma][1], qa[ks][ma*4+0], qa[ks][ma*4+1],
                            qa[ks][ma*4+2], qa[ks][ma*4+3], kb0[2], kb0[3]);
                    mma_f16(sc[ma][2], qa[ks][ma*4+0], qa[ks][ma*4+1],
                            qa[ks][ma*4+2], qa[ks][ma*4+3], kb1[0], kb1[1]);
                    mma_f16(sc[ma][3], qa[ks][ma*4+0], qa[ks][ma*4+1],
                            qa[ks][ma*4+2], qa[ks][ma*4+3], kb1[2], kb1[3]);
                }
            }

            if (k0h + 31 > qw) {
#pragma unroll
                for (int ma = 0; ma < 2; ma++) {
                    int r0g = qw + ma * 16 + gid;
                    int r1g = r0g + 8;
#pragma unroll
                    for (int nt = 0; nt < 4; nt++) {
                        int c = k0h + nt * 8 + 2 * tig;
                        if (c > r0g)     sc[ma][nt][0] = -1e30f;
                        if (c + 1 > r0g) sc[ma][nt][1] = -1e30f;
                        if (c > r1g)     sc[ma][nt][2] = -1e30f;
                        if (c + 1 > r1g) sc[ma][nt][3] = -1e30f;
                    }
                }
            }

            uint32_t pa[2][2][4];
#pragma unroll
            for (int ma = 0; ma < 2; ma++) {
                float mx0 = sc[ma][0][0], mx1 = sc[ma][0][2];
#pragma unroll
                for (int nt = 0; nt < 4; nt++) {
                    mx0 = fmaxf(mx0, fmaxf(sc[ma][nt][0], sc[ma][nt][1]));
                    mx1 = fmaxf(mx1, fmaxf(sc[ma][nt][2], sc[ma][nt][3]));
                }
                mx0 = fmaxf(mx0, __shfl_xor_sync(0xffffffffu, mx0, 1));
                mx0 = fmaxf(mx0, __shfl_xor_sync(0xffffffffu, mx0, 2));
                mx1 = fmaxf(mx1, __shfl_xor_sync(0xffffffffu, mx1, 1));
                mx1 = fmaxf(mx1, __shfl_xor_sync(0xffffffffu, mx1, 2));

                float mn0 = fmaxf(mm[ma][0], mx0);
                float mn1 = fmaxf(mm[ma][1], mx1);
                float al0 = ex2(mm[ma][0] - mn0);
                float al1 = ex2(mm[ma][1] - mn1);
                mm[ma][0] = mn0; mm[ma][1] = mn1;

                float sum0 = 0.0f, sum1 = 0.0f;
#pragma unroll
                for (int nt = 0; nt < 4; nt++) {
                    sc[ma][nt][0] = ex2(sc[ma][nt][0] - mn0);
                    sc[ma][nt][1] = ex2(sc[ma][nt][1] - mn0);
                    sc[ma][nt][2] = ex2(sc[ma][nt][2] - mn1);
                    sc[ma][nt][3] = ex2(sc[ma][nt][3] - mn1);
                    sum0 += sc[ma][nt][0] + sc[ma][nt][1];
                    sum1 += sc[ma][nt][2] + sc[ma][nt][3];
                }
                sum0 += __shfl_xor_sync(0xffffffffu, sum0, 1);
                sum0 += __shfl_xor_sync(0xffffffffu, sum0, 2);
                sum1 += __shfl_xor_sync(0xffffffffu, sum1, 1);
                sum1 += __shfl_xor_sync(0xffffffffu, sum1, 2);
                ll[ma][0] = ll[ma][0] * al0 + sum0;
                ll[ma][1] = ll[ma][1] * al1 + sum1;

#pragma unroll
                for (int nt = 0; nt < 8; nt++) {
                    of[ma][nt][0] *= al0; of[ma][nt][1] *= al0;
                    of[ma][nt][2] *= al1; of[ma][nt][3] *= al1;
                }

#pragma unroll
                for (int s = 0; s < 2; s++) {
                    pa[ma][s][0] = pack2(sc[ma][2*s][0], sc[ma][2*s][1]);
                    pa[ma][s][1] = pack2(sc[ma][2*s][2], sc[ma][2*s][3]);
                    pa[ma][s][2] = pack2(sc[ma][2*s+1][0], sc[ma][2*s+1][1]);
                    pa[ma][s][3] = pack2(sc[ma][2*s+1][2], sc[ma][2*s+1][3]);
                }
            }

#pragma unroll
            for (int s = 0; s < 2; s++) {
#pragma unroll
                for (int dp = 0; dp < 4; dp++) {
                    uint32_t vb[4];
                    ldm4t(vb, stg + v_lane + hoff + (uint32_t)s * 2304u +
                              (uint32_t)dp * 32u);
#pragma unroll
                    for (int ma = 0; ma < 2; ma++) {
                        mma_f16(of[ma][dp * 2], pa[ma][s][0], pa[ma][s][1],
                                pa[ma][s][2], pa[ma][s][3], vb[0], vb[1]);
                        mma_f16(of[ma][dp * 2 + 1], pa[ma][s][0], pa[ma][s][1],
                                pa[ma][s][2], pa[ma][s][3], vb[2], vb[3]);
                    }
                }
            }
        }
        cs++; if (cs == 3) cs = 0;
    }

#pragma unroll
    for (int ma = 0; ma < 2; ma++) {
        float inv0 = 1.0f / ll[ma][0];
        float inv1 = 1.0f / ll[ma][1];
        __half* O0 = g_oh + base + (size_t)(qw + ma * 16 + gid) * D_MODEL;
        __half* O1 = O0 + 8 * D_MODEL;
#pragma unroll
        for (int nt = 0; nt < 8; nt++) {
            int c = nt * 8 + 2 * tig;
            *(uint32_t*)&O0[c] = pack2(of[ma][nt][0] * inv0, of[ma][nt][1] * inv0);
            *(uint32_t*)&O1[c] = pack2(of[ma][nt][2] * inv1, of[ma][nt][3] * inv1);
        }
    }
}

// ---------------------------------------------------------------------------
// launcher: in-stream PDL chain (no events, no extra streams).
// ---------------------------------------------------------------------------
extern "C" void kernel_launch(void* const* d_in, const int* in_sizes, int n_in,
                              void* d_out, int out_size)
{
    const float* x  = (const float*)d_in[0];
    const float* wq = (const float*)d_in[1];
    const float* wk = (const float*)d_in[2];
    const float* wv = (const float*)d_in[3];
    const float* wo = (const float*)d_in[4];
    const int* tok  = (const int*)d_in[5];
    float* out = (float*)d_out;

    cudaFuncSetAttribute(gemm_qkv, cudaFuncAttributeMaxDynamicSharedMemorySize, GSMEM);
    cudaFuncSetAttribute(gemm_wo, cudaFuncAttributeMaxDynamicSharedMemorySize, GSMEM);
    cudaFuncSetAttribute(attn_f16, cudaFuncAttributeMaxDynamicSharedMemorySize, ASMEM);

    to_half<<<2048, 256>>>((const float4*)x, (const float4*)wq,
                           (const float4*)wk, (const float4*)wv,
                           (const float4*)wo, tok);

    cudaLaunchAttribute pa[1];
    pa[0].id = cudaLaunchAttributeProgrammaticStreamSerialization;
    pa[0].val.programmaticStreamSerializationAllowed = 1;

    {
        cudaLaunchConfig_t cfg = {};
        cfg.gridDim = dim3(24, MTOT / 128);   // (24, 64) fused QKV
        cfg.blockDim = dim3(128);
        cfg.dynamicSmemBytes = GSMEM;
        cfg.stream = 0;
        cfg.attrs = pa;
        cfg.numAttrs = 1;
        cudaLaunchKernelEx(&cfg, gemm_qkv);
    }
    {
        cudaLaunchConfig_t cfg = {};
        cfg.gridDim = dim3(SEQ / 128, BATCH * NUM_HEADS);   // (16, 64)
        cfg.blockDim = dim3(128);
        cfg.dynamicSmemBytes = ASMEM;
        cfg.stream = 0;
        cfg.attrs = pa;
        cfg.numAttrs = 1;
        cudaLaunchKernelEx(&cfg, attn_f16);
    }
    {
        cudaLaunchConfig_t cfg = {};
        cfg.gridDim = dim3(D_MODEL / 128, MTOT / 128);   // (8, 64)
        cfg.blockDim = dim3(128);
        cfg.dynamicSmemBytes = GSMEM;
        cfg.stream = 0;
        cfg.attrs = pa;
        cfg.numAttrs = 1;
        cudaLaunchKernelEx(&cfg, gemm_wo, out);
    }
}